// round 5
// baseline (speedup 1.0000x reference)
#include <cuda_runtime.h>
#include <cuda_bf16.h>
#include <cstdint>
#include <math.h>

#define NUM_EXPERTS 32
#define TOP_K 8
#define HIDDEN 1536
#define INTER 512
#define T_TOT 8192
#define CAP 8192
#define ROWS_TOT (T_TOT * TOP_K)

// ---------------- device scratch ----------------
__device__ int   g_cnt[NUM_EXPERTS];
__device__ int   g_off[NUM_EXPERTS];
__device__ int   g_tok[NUM_EXPERTS * CAP];
__device__ float g_wt [NUM_EXPERTS * CAP];
__device__ int   g_pair[T_TOT * TOP_K];
__device__ int   g_absmax[4];     // 0:x 1:w13 2:w2 3:h   (float bits, >=0)

__device__ int8_t g_xq1[(size_t)T_TOT * HIDDEN];
__device__ int8_t g_xq2[(size_t)T_TOT * HIDDEN];
__device__ int8_t g_w13q1[(size_t)NUM_EXPERTS * 2 * INTER * HIDDEN];
__device__ int8_t g_w13q2[(size_t)NUM_EXPERTS * 2 * INTER * HIDDEN];
__device__ int8_t g_w2q1[(size_t)NUM_EXPERTS * HIDDEN * INTER];
__device__ int8_t g_w2q2[(size_t)NUM_EXPERTS * HIDDEN * INTER];
__device__ float  g_hf[(size_t)ROWS_TOT * INTER];
__device__ int8_t g_hq1[(size_t)ROWS_TOT * INTER];
__device__ int8_t g_hq2[(size_t)ROWS_TOT * INTER];
__device__ float  g_y[(size_t)ROWS_TOT * HIDDEN];

// ---------------- helpers ----------------
__device__ __forceinline__ uint32_t smem_u32(const void* p) {
    uint32_t a;
    asm("{ .reg .u64 t; cvta.to.shared.u64 t, %1; cvt.u32.u64 %0, t; }" : "=r"(a) : "l"(p));
    return a;
}
__device__ __forceinline__ void cp16(uint32_t dst, const void* src, int sz) {
    asm volatile("cp.async.cg.shared.global [%0], [%1], 16, %2;"
                 :: "r"(dst), "l"(__cvta_generic_to_global(src)), "r"(sz));
}
#define CP_COMMIT() asm volatile("cp.async.commit_group;")
#define CP_WAIT1()  asm volatile("cp.async.wait_group 1;")

__device__ __forceinline__ void ldm4(uint32_t* r, uint32_t addr) {
    asm volatile("ldmatrix.sync.aligned.m8n8.x4.shared.b16 {%0,%1,%2,%3}, [%4];"
                 : "=r"(r[0]), "=r"(r[1]), "=r"(r[2]), "=r"(r[3]) : "r"(addr));
}
__device__ __forceinline__ void imma16832(int* c, const uint32_t* a, uint32_t b0, uint32_t b1) {
    asm volatile("mma.sync.aligned.m16n8k32.row.col.s32.s8.s8.s32 "
                 "{%0,%1,%2,%3}, {%4,%5,%6,%7}, {%8,%9}, {%0,%1,%2,%3};"
                 : "+r"(c[0]), "+r"(c[1]), "+r"(c[2]), "+r"(c[3])
                 : "r"(a[0]), "r"(a[1]), "r"(a[2]), "r"(a[3]), "r"(b0), "r"(b1));
}

// smem: 4 tiles (A1,A2,B1,B2) of 128 rows x 64 int8 (64B/row), 16B-chunk XOR swizzle
#define TILE_B  8192
#define OFF_A1  0
#define OFF_A2  8192
#define OFF_B1  16384
#define OFF_B2  24576
#define STAGE_B 32768
#define NST 3
#define SMEM_DYN (NST * STAGE_B)   // 98304

struct LoadCtx {
    const int8_t *a1, *a2, *b1, *b2;  // row base + (2*half)*16 elements
    int asz;
    uint32_t dst[2];                  // swizzled smem offsets for this thread's 2 chunks
};

__device__ __forceinline__ void load_stage(uint32_t sm, int st, int koff, const LoadCtx& c) {
    uint32_t b = sm + st * STAGE_B;
    #pragma unroll
    for (int j = 0; j < 2; j++) {
        cp16(b + OFF_A1 + c.dst[j], c.a1 + koff + j * 16, c.asz);
        cp16(b + OFF_A2 + c.dst[j], c.a2 + koff + j * 16, c.asz);
        cp16(b + OFF_B1 + c.dst[j], c.b1 + koff + j * 16, 16);
        cp16(b + OFF_B2 + c.dst[j], c.b2 + koff + j * 16, 16);
    }
}

// one BK=64 stage (2 k32 steps); warp tile 32x64
__device__ __forceinline__ void compute_stage(
        uint32_t sbase, int lane,
        const uint32_t arow[2], const uint32_t ar3[2],
        const uint32_t brow[4], const uint32_t br3[4],
        int acch[2][8][4], int accm[2][8][4]) {
    const uint32_t asel = lane >> 4;
    const uint32_t bsel = (lane >> 3) & 1;
    #pragma unroll
    for (int kk = 0; kk < 2; kk++) {
        uint32_t a1[2][4], a2[2][4];
        #pragma unroll
        for (int mi = 0; mi < 2; mi++) {
            uint32_t ch = 2 * kk + asel;
            uint32_t ad = sbase + OFF_A1 + arow[mi] + (((ch ^ ar3[mi]) & 3) << 4);
            ldm4(a1[mi], ad);
            ldm4(a2[mi], ad + (OFF_A2 - OFF_A1));
        }
        uint32_t b1[4][4], b2[4][4];
        #pragma unroll
        for (int q = 0; q < 4; q++) {
            uint32_t ch = 2 * kk + bsel;
            uint32_t bd = sbase + OFF_B1 + brow[q] + (((ch ^ br3[q]) & 3) << 4);
            ldm4(b1[q], bd);
            ldm4(b2[q], bd + (OFF_B2 - OFF_B1));
        }
        #pragma unroll
        for (int ni = 0; ni < 8; ni++)
            #pragma unroll
            for (int mi = 0; mi < 2; mi++)
                imma16832(acch[mi][ni], a1[mi], b1[ni >> 1][2 * (ni & 1)], b1[ni >> 1][2 * (ni & 1) + 1]);
        #pragma unroll
        for (int ni = 0; ni < 8; ni++)
            #pragma unroll
            for (int mi = 0; mi < 2; mi++)
                imma16832(accm[mi][ni], a1[mi], b2[ni >> 1][2 * (ni & 1)], b2[ni >> 1][2 * (ni & 1) + 1]);
        #pragma unroll
        for (int ni = 0; ni < 8; ni++)
            #pragma unroll
            for (int mi = 0; mi < 2; mi++)
                imma16832(accm[mi][ni], a2[mi], b1[ni >> 1][2 * (ni & 1)], b1[ni >> 1][2 * (ni & 1) + 1]);
    }
}

// ---------------- small kernels ----------------
__global__ void zero_cnt_kernel() {
    if (threadIdx.x < NUM_EXPERTS) g_cnt[threadIdx.x] = 0;
    if (threadIdx.x < 4) g_absmax[threadIdx.x] = 0;
}
__global__ void prefix_kernel() {
    if (threadIdx.x == 0) {
        int s = 0;
        for (int e = 0; e < NUM_EXPERTS; e++) { g_off[e] = s; s += g_cnt[e]; }
    }
}

__global__ void absmax_kernel(const float* __restrict__ src, size_t n4, int slot) {
    __shared__ float red[8];
    size_t i = (size_t)blockIdx.x * blockDim.x + threadIdx.x;
    size_t stride = (size_t)gridDim.x * blockDim.x;
    float m = 0.0f;
    for (; i < n4; i += stride) {
        float4 v = ((const float4*)src)[i];
        m = fmaxf(m, fmaxf(fmaxf(fabsf(v.x), fabsf(v.y)), fmaxf(fabsf(v.z), fabsf(v.w))));
    }
    #pragma unroll
    for (int o = 16; o > 0; o >>= 1) m = fmaxf(m, __shfl_xor_sync(0xffffffffu, m, o));
    if ((threadIdx.x & 31) == 0) red[threadIdx.x >> 5] = m;
    __syncthreads();
    if (threadIdx.x == 0) {
        float bm = 0.0f;
        #pragma unroll
        for (int w = 0; w < 8; w++) bm = fmaxf(bm, red[w]);
        atomicMax(&g_absmax[slot], __float_as_int(bm));
    }
}

__device__ __forceinline__ char q1of(float v, float inv1) {
    return (char)__float2int_rn(v * inv1);
}
__global__ void quant_kernel(const float* __restrict__ src, int8_t* __restrict__ q1,
                             int8_t* __restrict__ q2, size_t n4, int slot) {
    float mx = __int_as_float(g_absmax[slot]);
    float s1 = mx * (1.0f / 127.0f);
    float inv1 = 127.0f / mx;
    float inv2 = inv1 * 256.0f;
    size_t i = (size_t)blockIdx.x * blockDim.x + threadIdx.x;
    size_t stride = (size_t)gridDim.x * blockDim.x;
    for (; i < n4; i += stride) {
        float4 v = ((const float4*)src)[i];
        int a0 = __float2int_rn(v.x * inv1), a1 = __float2int_rn(v.y * inv1);
        int a2 = __float2int_rn(v.z * inv1), a3 = __float2int_rn(v.w * inv1);
        int b0 = min(127, max(-127, __float2int_rn((v.x - a0 * s1) * inv2)));
        int b1 = min(127, max(-127, __float2int_rn((v.y - a1 * s1) * inv2)));
        int b2 = min(127, max(-127, __float2int_rn((v.z - a2 * s1) * inv2)));
        int b3 = min(127, max(-127, __float2int_rn((v.w - a3 * s1) * inv2)));
        ((char4*)q1)[i] = make_char4((char)a0, (char)a1, (char)a2, (char)a3);
        ((char4*)q2)[i] = make_char4((char)b0, (char)b1, (char)b2, (char)b3);
    }
}

// quantize h (reads scale slot 3)
__global__ void hquant_kernel(size_t n4) {
    float mx = __int_as_float(g_absmax[3]);
    float s1 = mx * (1.0f / 127.0f);
    float inv1 = 127.0f / mx;
    float inv2 = inv1 * 256.0f;
    size_t i = (size_t)blockIdx.x * blockDim.x + threadIdx.x;
    size_t stride = (size_t)gridDim.x * blockDim.x;
    for (; i < n4; i += stride) {
        float4 v = ((const float4*)g_hf)[i];
        int a0 = __float2int_rn(v.x * inv1), a1 = __float2int_rn(v.y * inv1);
        int a2 = __float2int_rn(v.z * inv1), a3 = __float2int_rn(v.w * inv1);
        int b0 = min(127, max(-127, __float2int_rn((v.x - a0 * s1) * inv2)));
        int b1 = min(127, max(-127, __float2int_rn((v.y - a1 * s1) * inv2)));
        int b2 = min(127, max(-127, __float2int_rn((v.z - a2 * s1) * inv2)));
        int b3 = min(127, max(-127, __float2int_rn((v.w - a3 * s1) * inv2)));
        ((char4*)g_hq1)[i] = make_char4((char)a0, (char)a1, (char)a2, (char)a3);
        ((char4*)g_hq2)[i] = make_char4((char)b0, (char)b1, (char)b2, (char)b3);
    }
}

// ---------------- router ----------------
__global__ void router_kernel(const float* __restrict__ x, const float* __restrict__ gate_w) {
    const int t = blockIdx.x;
    const int tid = threadIdx.x;
    __shared__ float xs[HIDDEN];
    __shared__ float part[256];
    __shared__ float lg[NUM_EXPERTS];

    for (int i = tid * 4; i < HIDDEN; i += 256 * 4)
        *(float4*)&xs[i] = *(const float4*)&x[(size_t)t * HIDDEN + i];
    __syncthreads();

    const int e = tid & 31;
    const int p = tid >> 5;
    const float* gw = gate_w + (size_t)e * HIDDEN + p * 192;
    const float* xp = xs + p * 192;
    float s = 0.0f;
    #pragma unroll 4
    for (int i = 0; i < 192; i++) s += xp[i] * gw[i];
    part[tid] = s;
    __syncthreads();

    if (tid < NUM_EXPERTS) {
        float l = 0.0f;
        #pragma unroll
        for (int q = 0; q < 8; q++) l += part[q * 32 + tid];
        lg[tid] = l;
    }
    __syncthreads();

    if (tid == 0) {
        float mx = -INFINITY;
        #pragma unroll
        for (int i = 0; i < NUM_EXPERTS; i++) mx = fmaxf(mx, lg[i]);
        float pr[NUM_EXPERTS];
        #pragma unroll
        for (int i = 0; i < NUM_EXPERTS; i++) pr[i] = expf(lg[i] - mx);
        int idx[TOP_K]; float w[TOP_K]; float ws = 0.0f;
        unsigned used = 0u;
        for (int k = 0; k < TOP_K; k++) {
            int bi = -1; float bv = -INFINITY;
            for (int i = 0; i < NUM_EXPERTS; i++)
                if (!(used >> i & 1u) && pr[i] > bv) { bv = pr[i]; bi = i; }
            used |= 1u << bi; idx[k] = bi; w[k] = bv; ws += bv;
        }
        float inv = 1.0f / ws;
        for (int k = 0; k < TOP_K; k++) {
            int slot = atomicAdd(&g_cnt[idx[k]], 1);
            g_tok[idx[k] * CAP + slot] = t;
            g_wt [idx[k] * CAP + slot] = w[k] * inv;
            g_pair[t * TOP_K + k] = (idx[k] << 20) | slot;
        }
    }
}

// ---------------- GEMM1 (int8): gu = X @ W13^T, h = silu(g)*u -> g_hf ----------------
__global__ void __launch_bounds__(256) gemm1_kernel() {
    const int e = blockIdx.z;
    const int rows = g_cnt[e];
    const int rt = blockIdx.x;
    if (rt * 128 >= rows) return;
    const int ct = blockIdx.y;     // 0..7
    const int base = g_off[e];

    extern __shared__ char smraw[];
    __shared__ float s_hred[8];
    uint32_t sm = smem_u32(smraw);
    const int tid = threadIdx.x, wid = tid >> 5, lane = tid & 31;
    const int wm = wid >> 1, wn = wid & 1;

    LoadCtx c;
    {
        int r = tid >> 1;
        int half = tid & 1;
        int arow = rt * 128 + r;
        int v = arow < rows;
        int tok = v ? g_tok[e * CAP + arow] : 0;
        c.a1 = g_xq1 + (size_t)tok * HIDDEN + half * 32;
        c.a2 = g_xq2 + (size_t)tok * HIDDEN + half * 32;
        c.asz = v ? 16 : 0;
        int rh = (r >> 5) & 1, wnn = r >> 6, cc = r & 31;
        int w13row = rh * 512 + ct * 64 + wnn * 32 + cc;
        c.b1 = g_w13q1 + ((size_t)e * 1024 + w13row) * HIDDEN + half * 32;
        c.b2 = g_w13q2 + ((size_t)e * 1024 + w13row) * HIDDEN + half * 32;
        #pragma unroll
        for (int j = 0; j < 2; j++) {
            int ch = 2 * half + j;
            c.dst[j] = (uint32_t)(r * 64 + ((ch ^ (r & 3)) << 4));
        }
    }

    uint32_t arow[2], ar3[2], brow[4], br3[4];
    #pragma unroll
    for (int mi = 0; mi < 2; mi++) {
        uint32_t r = wm * 32 + mi * 16 + (lane & 15);
        arow[mi] = r << 6; ar3[mi] = r & 3;
    }
    #pragma unroll
    for (int q = 0; q < 4; q++) {
        uint32_t r = wn * 64 + q * 16 + (lane & 7) + ((lane >> 4) & 1) * 8;
        brow[q] = r << 6; br3[q] = r & 3;
    }

    int acch[2][8][4], accm[2][8][4];
    #pragma unroll
    for (int i = 0; i < 2; i++)
        #pragma unroll
        for (int j = 0; j < 8; j++)
            #pragma unroll
            for (int q = 0; q < 4; q++) { acch[i][j][q] = 0; accm[i][j][q] = 0; }

    const int NCH = HIDDEN / 64;   // 24
    load_stage(sm, 0, 0, c);  CP_COMMIT();
    load_stage(sm, 1, 64, c); CP_COMMIT();
    for (int k = 0; k < NCH; k++) {
        CP_WAIT1();
        __syncthreads();
        if (k + 2 < NCH) load_stage(sm, (k + 2) % NST, (k + 2) * 64, c);
        CP_COMMIT();
        compute_stage(sm + (k % NST) * STAGE_B, lane, arow, ar3, brow, br3, acch, accm);
    }

    const float sc = (__int_as_float(g_absmax[0]) * (1.0f / 127.0f)) *
                     (__int_as_float(g_absmax[1]) * (1.0f / 127.0f));
    const int lr = lane >> 2, lc = lane & 3;
    float tmax = 0.0f;
    #pragma unroll
    for (int mi = 0; mi < 2; mi++)
        #pragma unroll
        for (int half = 0; half < 2; half++) {
            int row = rt * 128 + wm * 32 + mi * 16 + lr + half * 8;
            if (row >= rows) continue;
            size_t hb = ((size_t)(base + row)) * INTER + ct * 64 + wn * 32 + lc * 2;
            #pragma unroll
            for (int ni = 0; ni < 4; ni++) {
                float g0 = sc * ((float)acch[mi][ni][2 * half]     + (float)accm[mi][ni][2 * half]     * 0.00390625f);
                float g1 = sc * ((float)acch[mi][ni][2 * half + 1] + (float)accm[mi][ni][2 * half + 1] * 0.00390625f);
                float u0 = sc * ((float)acch[mi][ni + 4][2 * half]     + (float)accm[mi][ni + 4][2 * half]     * 0.00390625f);
                float u1 = sc * ((float)acch[mi][ni + 4][2 * half + 1] + (float)accm[mi][ni + 4][2 * half + 1] * 0.00390625f);
                float h0 = g0 * u0 / (1.0f + __expf(-g0));
                float h1 = g1 * u1 / (1.0f + __expf(-g1));
                tmax = fmaxf(tmax, fmaxf(fabsf(h0), fabsf(h1)));
                *(float2*)(g_hf + hb + ni * 8) = make_float2(h0, h1);
            }
        }
    // block max |h| -> g_absmax[3]
    #pragma unroll
    for (int o = 16; o > 0; o >>= 1) tmax = fmaxf(tmax, __shfl_xor_sync(0xffffffffu, tmax, o));
    if (lane == 0) s_hred[wid] = tmax;
    __syncthreads();
    if (tid == 0) {
        float bm = 0.0f;
        #pragma unroll
        for (int w = 0; w < 8; w++) bm = fmaxf(bm, s_hred[w]);
        atomicMax(&g_absmax[3], __float_as_int(bm));
    }
}

// ---------------- GEMM2 (int8): y = wt * (h @ W2^T) ----------------
__global__ void __launch_bounds__(256) gemm2_kernel() {
    const int e = blockIdx.z;
    const int rows = g_cnt[e];
    const int rt = blockIdx.x;
    if (rt * 128 >= rows) return;
    const int ct = blockIdx.y;     // 0..11
    const int base = g_off[e];

    extern __shared__ char smraw[];
    uint32_t sm = smem_u32(smraw);
    const int tid = threadIdx.x, wid = tid >> 5, lane = tid & 31;
    const int wm = wid >> 1, wn = wid & 1;

    LoadCtx c;
    {
        int r = tid >> 1;
        int half = tid & 1;
        int arow = rt * 128 + r;
        int v = arow < rows;
        size_t hrow = (size_t)(base + (v ? arow : 0));
        c.a1 = g_hq1 + hrow * INTER + half * 32;
        c.a2 = g_hq2 + hrow * INTER + half * 32;
        c.asz = v ? 16 : 0;
        size_t brr = (size_t)e * HIDDEN + ct * 128 + r;
        c.b1 = g_w2q1 + brr * INTER + half * 32;
        c.b2 = g_w2q2 + brr * INTER + half * 32;
        #pragma unroll
        for (int j = 0; j < 2; j++) {
            int ch = 2 * half + j;
            c.dst[j] = (uint32_t)(r * 64 + ((ch ^ (r & 3)) << 4));
        }
    }

    uint32_t arow[2], ar3[2], brow[4], br3[4];
    #pragma unroll
    for (int mi = 0; mi < 2; mi++) {
        uint32_t r = wm * 32 + mi * 16 + (lane & 15);
        arow[mi] = r << 6; ar3[mi] = r & 3;
    }
    #pragma unroll
    for (int q = 0; q < 4; q++) {
        uint32_t r = wn * 64 + q * 16 + (lane & 7) + ((lane >> 4) & 1) * 8;
        brow[q] = r << 6; br3[q] = r & 3;
    }

    int acch[2][8][4], accm[2][8][4];
    #pragma unroll
    for (int i = 0; i < 2; i++)
        #pragma unroll
        for (int j = 0; j < 8; j++)
            #pragma unroll
            for (int q = 0; q < 4; q++) { acch[i][j][q] = 0; accm[i][j][q] = 0; }

    const int NCH = INTER / 64;    // 8
    load_stage(sm, 0, 0, c);  CP_COMMIT();
    load_stage(sm, 1, 64, c); CP_COMMIT();
    for (int k = 0; k < NCH; k++) {
        CP_WAIT1();
        __syncthreads();
        if (k + 2 < NCH) load_stage(sm, (k + 2) % NST, (k + 2) * 64, c);
        CP_COMMIT();
        compute_stage(sm + (k % NST) * STAGE_B, lane, arow, ar3, brow, br3, acch, accm);
    }

    const float sc = (__int_as_float(g_absmax[3]) * (1.0f / 127.0f)) *
                     (__int_as_float(g_absmax[2]) * (1.0f / 127.0f));
    const int lr = lane >> 2, lc = lane & 3;
    #pragma unroll
    for (int mi = 0; mi < 2; mi++)
        #pragma unroll
        for (int half = 0; half < 2; half++) {
            int row = rt * 128 + wm * 32 + mi * 16 + lr + half * 8;
            if (row >= rows) continue;
            float w = g_wt[e * CAP + row] * sc;
            float* yp = g_y + (size_t)(base + row) * HIDDEN + ct * 128 + wn * 64 + lc * 2;
            #pragma unroll
            for (int ni = 0; ni < 8; ni++) {
                float2 v;
                v.x = w * ((float)acch[mi][ni][2 * half]     + (float)accm[mi][ni][2 * half]     * 0.00390625f);
                v.y = w * ((float)acch[mi][ni][2 * half + 1] + (float)accm[mi][ni][2 * half + 1] * 0.00390625f);
                *(float2*)(yp + ni * 8) = v;
            }
        }
}

// ---------------- gather ----------------
__global__ void gather_kernel(float* __restrict__ out) {
    const int t = blockIdx.x;
    int rowid[TOP_K];
    #pragma unroll
    for (int k = 0; k < TOP_K; k++) {
        int pp = g_pair[t * TOP_K + k];
        rowid[k] = g_off[pp >> 20] + (pp & 0xFFFFF);
    }
    for (int cc = threadIdx.x * 4; cc < HIDDEN; cc += blockDim.x * 4) {
        float4 acc = make_float4(0.f, 0.f, 0.f, 0.f);
        #pragma unroll
        for (int k = 0; k < TOP_K; k++) {
            float4 v = *(const float4*)(g_y + (size_t)rowid[k] * HIDDEN + cc);
            acc.x += v.x; acc.y += v.y; acc.z += v.z; acc.w += v.w;
        }
        *(float4*)(out + (size_t)t * HIDDEN + cc) = acc;
    }
}

// ---------------- launch ----------------
extern "C" void kernel_launch(void* const* d_in, const int* in_sizes, int n_in,
                              void* d_out, int out_size) {
    const float* x      = (const float*)d_in[0];
    const float* gate_w = (const float*)d_in[1];
    const float* w13    = (const float*)d_in[2];
    const float* w2     = (const float*)d_in[3];
    float* out = (float*)d_out;

    cudaFuncSetAttribute(gemm1_kernel, cudaFuncAttributeMaxDynamicSharedMemorySize, SMEM_DYN);
    cudaFuncSetAttribute(gemm2_kernel, cudaFuncAttributeMaxDynamicSharedMemorySize, SMEM_DYN);

    int8_t *xq1, *xq2, *w13q1, *w13q2, *w2q1, *w2q2;
    cudaGetSymbolAddress((void**)&xq1,   g_xq1);
    cudaGetSymbolAddress((void**)&xq2,   g_xq2);
    cudaGetSymbolAddress((void**)&w13q1, g_w13q1);
    cudaGetSymbolAddress((void**)&w13q2, g_w13q2);
    cudaGetSymbolAddress((void**)&w2q1,  g_w2q1);
    cudaGetSymbolAddress((void**)&w2q2,  g_w2q2);

    const size_t nx   = (size_t)T_TOT * HIDDEN / 4;
    const size_t nw13 = (size_t)NUM_EXPERTS * 2 * INTER * HIDDEN / 4;
    const size_t nw2  = (size_t)NUM_EXPERTS * HIDDEN * INTER / 4;
    const size_t nh   = (size_t)ROWS_TOT * INTER / 4;

    zero_cnt_kernel<<<1, 32>>>();
    router_kernel<<<T_TOT, 256>>>(x, gate_w);
    prefix_kernel<<<1, 32>>>();
    absmax_kernel<<<1024, 256>>>(x,   nx,   0);
    absmax_kernel<<<2048, 256>>>(w13, nw13, 1);
    absmax_kernel<<<2048, 256>>>(w2,  nw2,  2);
    quant_kernel<<<2048, 256>>>(x,   xq1,   xq2,   nx,   0);
    quant_kernel<<<4096, 256>>>(w13, w13q1, w13q2, nw13, 1);
    quant_kernel<<<4096, 256>>>(w2,  w2q1,  w2q2,  nw2,  2);
    gemm1_kernel<<<dim3(T_TOT / 128, INTER / 64, NUM_EXPERTS), 256, SMEM_DYN>>>();
    hquant_kernel<<<4096, 256>>>(nh);
    gemm2_kernel<<<dim3(T_TOT / 128, HIDDEN / 128, NUM_EXPERTS), 256, SMEM_DYN>>>();
    gather_kernel<<<T_TOT, 128>>>(out);
}

// round 6
// speedup vs baseline: 3.0254x; 3.0254x over previous
#include <cuda_runtime.h>
#include <cuda_fp16.h>
#include <cstdint>
#include <math.h>

#define NUM_EXPERTS 32
#define TOP_K 8
#define HIDDEN 1536
#define INTER 512
#define T_TOT 8192
#define CAP 8192
#define ROWS_TOT (T_TOT * TOP_K)

// ---------------- device scratch ----------------
__device__ int   g_cnt[NUM_EXPERTS];
__device__ int   g_off[NUM_EXPERTS];
__device__ int   g_tok[NUM_EXPERTS * CAP];
__device__ float g_wt [NUM_EXPERTS * CAP];
__device__ int   g_pair[T_TOT * TOP_K];

__device__ __half g_xh[(size_t)T_TOT * HIDDEN];
__device__ __half g_w13h[(size_t)NUM_EXPERTS * 2 * INTER * HIDDEN];
__device__ __half g_w2h[(size_t)NUM_EXPERTS * HIDDEN * INTER];
__device__ __half g_h[(size_t)ROWS_TOT * INTER];
__device__ __half g_y[(size_t)ROWS_TOT * HIDDEN];

// ---------------- helpers ----------------
__device__ __forceinline__ uint32_t smem_u32(const void* p) {
    uint32_t a;
    asm("{ .reg .u64 t; cvta.to.shared.u64 t, %1; cvt.u32.u64 %0, t; }" : "=r"(a) : "l"(p));
    return a;
}
__device__ __forceinline__ void cp16(uint32_t dst, const void* src, int sz) {
    asm volatile("cp.async.cg.shared.global [%0], [%1], 16, %2;"
                 :: "r"(dst), "l"(__cvta_generic_to_global(src)), "r"(sz));
}
#define CP_COMMIT() asm volatile("cp.async.commit_group;")
#define CP_WAIT1()  asm volatile("cp.async.wait_group 1;")

__device__ __forceinline__ void ldm4(uint32_t* r, uint32_t addr) {
    asm volatile("ldmatrix.sync.aligned.m8n8.x4.shared.b16 {%0,%1,%2,%3}, [%4];"
                 : "=r"(r[0]), "=r"(r[1]), "=r"(r[2]), "=r"(r[3]) : "r"(addr));
}
__device__ __forceinline__ void mma16816(float* c, const uint32_t* a, uint32_t b0, uint32_t b1) {
    asm volatile("mma.sync.aligned.m16n8k16.row.col.f32.f16.f16.f32 "
                 "{%0,%1,%2,%3}, {%4,%5,%6,%7}, {%8,%9}, {%0,%1,%2,%3};"
                 : "+f"(c[0]), "+f"(c[1]), "+f"(c[2]), "+f"(c[3])
                 : "r"(a[0]), "r"(a[1]), "r"(a[2]), "r"(a[3]), "r"(b0), "r"(b1));
}

// smem: 2 tiles (A, B) of 128 rows x 64 fp16 = 128B/row, 16B-chunk XOR swizzle
#define TILE_B  16384
#define OFF_A   0
#define OFF_B   16384
#define STAGE_B 32768
#define NST 3
#define SMEM_DYN (NST * STAGE_B)   // 98304

struct LoadCtx {
    const __half *a, *b;     // row base + kc0*8 elements
    int asz;
    uint32_t dst[4];         // swizzled smem offsets for this thread's 4 chunks
};

__device__ __forceinline__ void load_stage(uint32_t sm, int st, int koff, const LoadCtx& c) {
    uint32_t b = sm + st * STAGE_B;
    #pragma unroll
    for (int j = 0; j < 4; j++) {
        cp16(b + OFF_A + c.dst[j], c.a + koff + j * 8, c.asz);
        cp16(b + OFF_B + c.dst[j], c.b + koff + j * 8, 16);
    }
}

// one BK=64 stage (4 k16 steps); warp tile 32x64; 16 independent accumulators
__device__ __forceinline__ void compute_stage(
        uint32_t sbase, int lane,
        const uint32_t arow[2], const uint32_t ar7[2],
        const uint32_t brow[4], const uint32_t br7[4],
        float acc[2][8][4]) {
    const uint32_t asel = lane >> 4;
    const uint32_t bsel = (lane >> 3) & 1;
    #pragma unroll
    for (int kk = 0; kk < 4; kk++) {
        uint32_t a[2][4];
        #pragma unroll
        for (int mi = 0; mi < 2; mi++) {
            uint32_t ch = kk * 2 + asel;
            ldm4(a[mi], sbase + OFF_A + arow[mi] + (((ch ^ ar7[mi]) & 7) << 4));
        }
        uint32_t b[4][4];
        #pragma unroll
        for (int q = 0; q < 4; q++) {
            uint32_t ch = kk * 2 + bsel;
            ldm4(b[q], sbase + OFF_B + brow[q] + (((ch ^ br7[q]) & 7) << 4));
        }
        #pragma unroll
        for (int ni = 0; ni < 8; ni++)
            #pragma unroll
            for (int mi = 0; mi < 2; mi++)
                mma16816(acc[mi][ni], a[mi], b[ni >> 1][2 * (ni & 1)], b[ni >> 1][2 * (ni & 1) + 1]);
    }
}

// ---------------- small kernels ----------------
__global__ void zero_cnt_kernel() {
    if (threadIdx.x < NUM_EXPERTS) g_cnt[threadIdx.x] = 0;
}
__global__ void prefix_kernel() {
    if (threadIdx.x == 0) {
        int s = 0;
        for (int e = 0; e < NUM_EXPERTS; e++) { g_off[e] = s; s += g_cnt[e]; }
    }
}
__global__ void tohalf_kernel(const float* __restrict__ src, __half* __restrict__ dst, size_t n4) {
    size_t i = (size_t)blockIdx.x * blockDim.x + threadIdx.x;
    size_t stride = (size_t)gridDim.x * blockDim.x;
    for (; i < n4; i += stride) {
        float4 v = ((const float4*)src)[i];
        __half2* dp = (__half2*)dst;
        dp[2 * i]     = __floats2half2_rn(v.x, v.y);
        dp[2 * i + 1] = __floats2half2_rn(v.z, v.w);
    }
}

// ---------------- router ----------------
__global__ void router_kernel(const float* __restrict__ x, const float* __restrict__ gate_w) {
    const int t = blockIdx.x;
    const int tid = threadIdx.x;
    __shared__ float xs[HIDDEN];
    __shared__ float part[256];
    __shared__ float lg[NUM_EXPERTS];

    for (int i = tid * 4; i < HIDDEN; i += 256 * 4)
        *(float4*)&xs[i] = *(const float4*)&x[(size_t)t * HIDDEN + i];
    __syncthreads();

    const int e = tid & 31;
    const int p = tid >> 5;
    const float* gw = gate_w + (size_t)e * HIDDEN + p * 192;
    const float* xp = xs + p * 192;
    float s = 0.0f;
    #pragma unroll 4
    for (int i = 0; i < 192; i++) s += xp[i] * gw[i];
    part[tid] = s;
    __syncthreads();

    if (tid < NUM_EXPERTS) {
        float l = 0.0f;
        #pragma unroll
        for (int q = 0; q < 8; q++) l += part[q * 32 + tid];
        lg[tid] = l;
    }
    __syncthreads();

    if (tid == 0) {
        float mx = -INFINITY;
        #pragma unroll
        for (int i = 0; i < NUM_EXPERTS; i++) mx = fmaxf(mx, lg[i]);
        float pr[NUM_EXPERTS];
        #pragma unroll
        for (int i = 0; i < NUM_EXPERTS; i++) pr[i] = expf(lg[i] - mx);
        int idx[TOP_K]; float w[TOP_K]; float ws = 0.0f;
        unsigned used = 0u;
        for (int k = 0; k < TOP_K; k++) {
            int bi = -1; float bv = -INFINITY;
            for (int i = 0; i < NUM_EXPERTS; i++)
                if (!(used >> i & 1u) && pr[i] > bv) { bv = pr[i]; bi = i; }
            used |= 1u << bi; idx[k] = bi; w[k] = bv; ws += bv;
        }
        float inv = 1.0f / ws;
        for (int k = 0; k < TOP_K; k++) {
            int slot = atomicAdd(&g_cnt[idx[k]], 1);
            g_tok[idx[k] * CAP + slot] = t;
            g_wt [idx[k] * CAP + slot] = w[k] * inv;
            g_pair[t * TOP_K + k] = (idx[k] << 20) | slot;
        }
    }
}

// ---------------- GEMM1 (fp16 HMMA): gu = X @ W13^T, h = silu(g)*u -> g_h ----------------
__global__ void __launch_bounds__(256, 1) gemm1_kernel() {
    const int e = blockIdx.z;
    const int rows = g_cnt[e];
    const int rt = blockIdx.x;
    if (rt * 128 >= rows) return;
    const int ct = blockIdx.y;     // 0..7 : g/u cols ct*64..+64
    const int base = g_off[e];

    extern __shared__ char smraw[];
    uint32_t sm = smem_u32(smraw);
    const int tid = threadIdx.x, wid = tid >> 5, lane = tid & 31;
    const int wm = wid >> 1, wn = wid & 1;

    LoadCtx c;
    {
        int r = tid >> 1;          // 0..127
        int kc0 = (tid & 1) * 4;   // first of 4 chunks
        int arow = rt * 128 + r;
        int v = arow < rows;
        int tok = v ? g_tok[e * CAP + arow] : 0;
        c.a = g_xh + (size_t)tok * HIDDEN + kc0 * 8;
        c.asz = v ? 16 : 0;
        int half = (r >> 5) & 1, wnn = r >> 6, cc = r & 31;
        int w13row = half * 512 + ct * 64 + wnn * 32 + cc;
        c.b = g_w13h + ((size_t)e * 1024 + w13row) * HIDDEN + kc0 * 8;
        #pragma unroll
        for (int j = 0; j < 4; j++)
            c.dst[j] = (uint32_t)(r * 128 + (((kc0 + j) ^ (r & 7)) << 4));
    }

    uint32_t arow[2], ar7[2], brow[4], br7[4];
    #pragma unroll
    for (int mi = 0; mi < 2; mi++) {
        uint32_t r = wm * 32 + mi * 16 + (lane & 15);
        arow[mi] = r << 7; ar7[mi] = r & 7;
    }
    #pragma unroll
    for (int q = 0; q < 4; q++) {
        uint32_t r = wn * 64 + q * 16 + (lane & 7) + ((lane >> 4) & 1) * 8;
        brow[q] = r << 7; br7[q] = r & 7;
    }

    float acc[2][8][4];
    #pragma unroll
    for (int i = 0; i < 2; i++)
        #pragma unroll
        for (int j = 0; j < 8; j++)
            #pragma unroll
            for (int q = 0; q < 4; q++) acc[i][j][q] = 0.0f;

    const int NCH = HIDDEN / 64;   // 24
    load_stage(sm, 0, 0, c);  CP_COMMIT();
    load_stage(sm, 1, 64, c); CP_COMMIT();
    for (int k = 0; k < NCH; k++) {
        CP_WAIT1();
        __syncthreads();
        if (k + 2 < NCH) load_stage(sm, (k + 2) % NST, (k + 2) * 64, c);
        CP_COMMIT();
        compute_stage(sm + (k % NST) * STAGE_B, lane, arow, ar7, brow, br7, acc);
    }

    // epilogue: ni 0..3 = g, ni+4 = u ; h = silu(g)*u -> fp16
    const int lr = lane >> 2, lc = lane & 3;
    #pragma unroll
    for (int mi = 0; mi < 2; mi++)
        #pragma unroll
        for (int half = 0; half < 2; half++) {
            int row = rt * 128 + wm * 32 + mi * 16 + lr + half * 8;
            if (row >= rows) continue;
            size_t hb = ((size_t)(base + row)) * INTER + ct * 64 + wn * 32 + lc * 2;
            #pragma unroll
            for (int ni = 0; ni < 4; ni++) {
                float g0 = acc[mi][ni][2 * half],     u0 = acc[mi][ni + 4][2 * half];
                float g1 = acc[mi][ni][2 * half + 1], u1 = acc[mi][ni + 4][2 * half + 1];
                float h0 = g0 * u0 / (1.0f + __expf(-g0));
                float h1 = g1 * u1 / (1.0f + __expf(-g1));
                *(__half2*)(g_h + hb + ni * 8) = __floats2half2_rn(h0, h1);
            }
        }
}

// ---------------- GEMM2 (fp16 HMMA): y = wt * (h @ W2^T) -> fp16 ----------------
__global__ void __launch_bounds__(256, 1) gemm2_kernel() {
    const int e = blockIdx.z;
    const int rows = g_cnt[e];
    const int rt = blockIdx.x;
    if (rt * 128 >= rows) return;
    const int ct = blockIdx.y;     // 0..11
    const int base = g_off[e];

    extern __shared__ char smraw[];
    uint32_t sm = smem_u32(smraw);
    const int tid = threadIdx.x, wid = tid >> 5, lane = tid & 31;
    const int wm = wid >> 1, wn = wid & 1;

    LoadCtx c;
    {
        int r = tid >> 1;
        int kc0 = (tid & 1) * 4;
        int arow = rt * 128 + r;
        int v = arow < rows;
        size_t hrow = (size_t)(base + (v ? arow : 0));
        c.a = g_h + hrow * INTER + kc0 * 8;
        c.asz = v ? 16 : 0;
        size_t brr = (size_t)e * HIDDEN + ct * 128 + r;
        c.b = g_w2h + brr * INTER + kc0 * 8;
        #pragma unroll
        for (int j = 0; j < 4; j++)
            c.dst[j] = (uint32_t)(r * 128 + (((kc0 + j) ^ (r & 7)) << 4));
    }

    uint32_t arow[2], ar7[2], brow[4], br7[4];
    #pragma unroll
    for (int mi = 0; mi < 2; mi++) {
        uint32_t r = wm * 32 + mi * 16 + (lane & 15);
        arow[mi] = r << 7; ar7[mi] = r & 7;
    }
    #pragma unroll
    for (int q = 0; q < 4; q++) {
        uint32_t r = wn * 64 + q * 16 + (lane & 7) + ((lane >> 4) & 1) * 8;
        brow[q] = r << 7; br7[q] = r & 7;
    }

    float acc[2][8][4];
    #pragma unroll
    for (int i = 0; i < 2; i++)
        #pragma unroll
        for (int j = 0; j < 8; j++)
            #pragma unroll
            for (int q = 0; q < 4; q++) acc[i][j][q] = 0.0f;

    const int NCH = INTER / 64;    // 8
    load_stage(sm, 0, 0, c);  CP_COMMIT();
    load_stage(sm, 1, 64, c); CP_COMMIT();
    for (int k = 0; k < NCH; k++) {
        CP_WAIT1();
        __syncthreads();
        if (k + 2 < NCH) load_stage(sm, (k + 2) % NST, (k + 2) * 64, c);
        CP_COMMIT();
        compute_stage(sm + (k % NST) * STAGE_B, lane, arow, ar7, brow, br7, acc);
    }

    const int lr = lane >> 2, lc = lane & 3;
    #pragma unroll
    for (int mi = 0; mi < 2; mi++)
        #pragma unroll
        for (int half = 0; half < 2; half++) {
            int row = rt * 128 + wm * 32 + mi * 16 + lr + half * 8;
            if (row >= rows) continue;
            float w = g_wt[e * CAP + row];
            __half* yp = g_y + (size_t)(base + row) * HIDDEN + ct * 128 + wn * 64 + lc * 2;
            #pragma unroll
            for (int ni = 0; ni < 8; ni++)
                *(__half2*)(yp + ni * 8) =
                    __floats2half2_rn(w * acc[mi][ni][2 * half], w * acc[mi][ni][2 * half + 1]);
        }
}

// ---------------- gather: out[t] = sum_k y[row_k] (fp32 accumulate) ----------------
__global__ void gather_kernel(float* __restrict__ out) {
    const int t = blockIdx.x;
    int rowid[TOP_K];
    #pragma unroll
    for (int k = 0; k < TOP_K; k++) {
        int pp = g_pair[t * TOP_K + k];
        rowid[k] = g_off[pp >> 20] + (pp & 0xFFFFF);
    }
    for (int cc = threadIdx.x * 8; cc < HIDDEN; cc += blockDim.x * 8) {
        float acc[8] = {};
        #pragma unroll
        for (int k = 0; k < TOP_K; k++) {
            uint4 raw = *(const uint4*)(g_y + (size_t)rowid[k] * HIDDEN + cc);
            const __half2* hp = (const __half2*)&raw;
            #pragma unroll
            for (int j = 0; j < 4; j++) {
                float2 v = __half22float2(hp[j]);
                acc[2 * j] += v.x; acc[2 * j + 1] += v.y;
            }
        }
        float4* op = (float4*)(out + (size_t)t * HIDDEN + cc);
        op[0] = make_float4(acc[0], acc[1], acc[2], acc[3]);
        op[1] = make_float4(acc[4], acc[5], acc[6], acc[7]);
    }
}

// ---------------- launch ----------------
extern "C" void kernel_launch(void* const* d_in, const int* in_sizes, int n_in,
                              void* d_out, int out_size) {
    const float* x      = (const float*)d_in[0];
    const float* gate_w = (const float*)d_in[1];
    const float* w13    = (const float*)d_in[2];
    const float* w2     = (const float*)d_in[3];
    float* out = (float*)d_out;

    cudaFuncSetAttribute(gemm1_kernel, cudaFuncAttributeMaxDynamicSharedMemorySize, SMEM_DYN);
    cudaFuncSetAttribute(gemm2_kernel, cudaFuncAttributeMaxDynamicSharedMemorySize, SMEM_DYN);

    __half *xh, *w13h, *w2h;
    cudaGetSymbolAddress((void**)&xh,   g_xh);
    cudaGetSymbolAddress((void**)&w13h, g_w13h);
    cudaGetSymbolAddress((void**)&w2h,  g_w2h);

    zero_cnt_kernel<<<1, 32>>>();
    router_kernel<<<T_TOT, 256>>>(x, gate_w);
    prefix_kernel<<<1, 32>>>();
    tohalf_kernel<<<2048, 256>>>(x,   xh,   (size_t)T_TOT * HIDDEN / 4);
    tohalf_kernel<<<4096, 256>>>(w13, w13h, (size_t)NUM_EXPERTS * 2 * INTER * HIDDEN / 4);
    tohalf_kernel<<<4096, 256>>>(w2,  w2h,  (size_t)NUM_EXPERTS * HIDDEN * INTER / 4);
    gemm1_kernel<<<dim3(T_TOT / 128, INTER / 64, NUM_EXPERTS), 256, SMEM_DYN>>>();
    gemm2_kernel<<<dim3(T_TOT / 128, HIDDEN / 128, NUM_EXPERTS), 256, SMEM_DYN>>>();
    gather_kernel<<<T_TOT, 128>>>(out);
}

// round 7
// speedup vs baseline: 3.0669x; 1.0137x over previous
#include <cuda_runtime.h>
#include <cuda_fp16.h>
#include <cstdint>
#include <math.h>

#define NUM_EXPERTS 32
#define TOP_K 8
#define HIDDEN 1536
#define INTER 512
#define T_TOT 8192
#define CAP 8192
#define ROWS_TOT (T_TOT * TOP_K)

// ---------------- device scratch ----------------
__device__ int   g_cnt[NUM_EXPERTS];
__device__ int   g_off[NUM_EXPERTS];
__device__ int   g_tok[NUM_EXPERTS * CAP];
__device__ float g_wt [NUM_EXPERTS * CAP];
__device__ int   g_pair[T_TOT * TOP_K];

__device__ __half g_xh[(size_t)T_TOT * HIDDEN];
__device__ __half g_w13h[(size_t)NUM_EXPERTS * 2 * INTER * HIDDEN];
__device__ __half g_w2h[(size_t)NUM_EXPERTS * HIDDEN * INTER];
__device__ __half g_h[(size_t)ROWS_TOT * INTER];
__device__ __half g_y[(size_t)ROWS_TOT * HIDDEN];

// ---------------- helpers ----------------
__device__ __forceinline__ uint32_t smem_u32(const void* p) {
    uint32_t a;
    asm("{ .reg .u64 t; cvta.to.shared.u64 t, %1; cvt.u32.u64 %0, t; }" : "=r"(a) : "l"(p));
    return a;
}
__device__ __forceinline__ void cp16(uint32_t dst, const void* src, int sz) {
    asm volatile("cp.async.cg.shared.global [%0], [%1], 16, %2;"
                 :: "r"(dst), "l"(__cvta_generic_to_global(src)), "r"(sz));
}
#define CP_COMMIT() asm volatile("cp.async.commit_group;")
#define CP_WAIT1()  asm volatile("cp.async.wait_group 1;")

__device__ __forceinline__ void ldm4(uint32_t* r, uint32_t addr) {
    asm volatile("ldmatrix.sync.aligned.m8n8.x4.shared.b16 {%0,%1,%2,%3}, [%4];"
                 : "=r"(r[0]), "=r"(r[1]), "=r"(r[2]), "=r"(r[3]) : "r"(addr));
}
__device__ __forceinline__ void mma16816(float* c, const uint32_t* a, uint32_t b0, uint32_t b1) {
    asm volatile("mma.sync.aligned.m16n8k16.row.col.f32.f16.f16.f32 "
                 "{%0,%1,%2,%3}, {%4,%5,%6,%7}, {%8,%9}, {%0,%1,%2,%3};"
                 : "+f"(c[0]), "+f"(c[1]), "+f"(c[2]), "+f"(c[3])
                 : "r"(a[0]), "r"(a[1]), "r"(a[2]), "r"(a[3]), "r"(b0), "r"(b1));
}

// smem: 2 tiles (A, B) of 128 rows x 64 fp16 = 128B/row, 16B-chunk XOR swizzle
#define TILE_B  16384
#define OFF_A   0
#define OFF_B   16384
#define STAGE_B 32768
#define NST 3
#define SMEM_DYN (NST * STAGE_B)   // 98304

struct LoadCtx {
    const __half *a, *b;     // row base + kc0*8 elements
    int asz;
    uint32_t dst[4];         // swizzled smem offsets for this thread's 4 chunks
};

__device__ __forceinline__ void load_stage(uint32_t sm, int st, int koff, const LoadCtx& c) {
    uint32_t b = sm + st * STAGE_B;
    #pragma unroll
    for (int j = 0; j < 4; j++) {
        cp16(b + OFF_A + c.dst[j], c.a + koff + j * 8, c.asz);
        cp16(b + OFF_B + c.dst[j], c.b + koff + j * 8, 16);
    }
}

// one BK=64 stage (4 k16 steps); warp tile 32x64; 16 independent accumulators
__device__ __forceinline__ void compute_stage(
        uint32_t sbase, int lane,
        const uint32_t arow[2], const uint32_t ar7[2],
        const uint32_t brow[4], const uint32_t br7[4],
        float acc[2][8][4]) {
    const uint32_t asel = lane >> 4;
    const uint32_t bsel = (lane >> 3) & 1;
    #pragma unroll
    for (int kk = 0; kk < 4; kk++) {
        uint32_t a[2][4];
        #pragma unroll
        for (int mi = 0; mi < 2; mi++) {
            uint32_t ch = kk * 2 + asel;
            ldm4(a[mi], sbase + OFF_A + arow[mi] + (((ch ^ ar7[mi]) & 7) << 4));
        }
        uint32_t b[4][4];
        #pragma unroll
        for (int q = 0; q < 4; q++) {
            uint32_t ch = kk * 2 + bsel;
            ldm4(b[q], sbase + OFF_B + brow[q] + (((ch ^ br7[q]) & 7) << 4));
        }
        #pragma unroll
        for (int ni = 0; ni < 8; ni++)
            #pragma unroll
            for (int mi = 0; mi < 2; mi++)
                mma16816(acc[mi][ni], a[mi], b[ni >> 1][2 * (ni & 1)], b[ni >> 1][2 * (ni & 1) + 1]);
    }
}

// ---------------- small kernels ----------------
__global__ void zero_cnt_kernel() {
    if (threadIdx.x < NUM_EXPERTS) g_cnt[threadIdx.x] = 0;
}
__global__ void prefix_kernel() {
    if (threadIdx.x == 0) {
        int s = 0;
        for (int e = 0; e < NUM_EXPERTS; e++) { g_off[e] = s; s += g_cnt[e]; }
    }
}
__global__ void tohalf_kernel(const float* __restrict__ src, __half* __restrict__ dst, size_t n8) {
    size_t i = (size_t)blockIdx.x * blockDim.x + threadIdx.x;
    size_t stride = (size_t)gridDim.x * blockDim.x;
    for (; i < n8; i += stride) {
        float4 v0 = ((const float4*)src)[2 * i];
        float4 v1 = ((const float4*)src)[2 * i + 1];
        uint4 o;
        __half2 h0 = __floats2half2_rn(v0.x, v0.y);
        __half2 h1 = __floats2half2_rn(v0.z, v0.w);
        __half2 h2 = __floats2half2_rn(v1.x, v1.y);
        __half2 h3 = __floats2half2_rn(v1.z, v1.w);
        o.x = *(uint32_t*)&h0; o.y = *(uint32_t*)&h1;
        o.z = *(uint32_t*)&h2; o.w = *(uint32_t*)&h3;
        ((uint4*)dst)[i] = o;
    }
}

// ---------------- router ----------------
__global__ void router_kernel(const float* __restrict__ x, const float* __restrict__ gate_w) {
    const int t = blockIdx.x;
    const int tid = threadIdx.x;
    __shared__ float xs[HIDDEN];
    __shared__ float part[256];
    __shared__ float lg[NUM_EXPERTS];

    for (int i = tid * 4; i < HIDDEN; i += 256 * 4)
        *(float4*)&xs[i] = *(const float4*)&x[(size_t)t * HIDDEN + i];
    __syncthreads();

    const int e = tid & 31;
    const int p = tid >> 5;
    const float* gw = gate_w + (size_t)e * HIDDEN + p * 192;
    const float* xp = xs + p * 192;
    float s = 0.0f;
    #pragma unroll 4
    for (int i = 0; i < 192; i++) s += xp[i] * gw[i];
    part[tid] = s;
    __syncthreads();

    if (tid < NUM_EXPERTS) {
        float l = 0.0f;
        #pragma unroll
        for (int q = 0; q < 8; q++) l += part[q * 32 + tid];
        lg[tid] = l;
    }
    __syncthreads();

    if (tid == 0) {
        float mx = -INFINITY;
        #pragma unroll
        for (int i = 0; i < NUM_EXPERTS; i++) mx = fmaxf(mx, lg[i]);
        float pr[NUM_EXPERTS];
        #pragma unroll
        for (int i = 0; i < NUM_EXPERTS; i++) pr[i] = expf(lg[i] - mx);
        int idx[TOP_K]; float w[TOP_K]; float ws = 0.0f;
        unsigned used = 0u;
        for (int k = 0; k < TOP_K; k++) {
            int bi = -1; float bv = -INFINITY;
            for (int i = 0; i < NUM_EXPERTS; i++)
                if (!(used >> i & 1u) && pr[i] > bv) { bv = pr[i]; bi = i; }
            used |= 1u << bi; idx[k] = bi; w[k] = bv; ws += bv;
        }
        float inv = 1.0f / ws;
        for (int k = 0; k < TOP_K; k++) {
            int slot = atomicAdd(&g_cnt[idx[k]], 1);
            g_tok[idx[k] * CAP + slot] = t;
            g_wt [idx[k] * CAP + slot] = w[k] * inv;
            g_pair[t * TOP_K + k] = (idx[k] << 20) | slot;
        }
    }
}

// ---------------- GEMM1 (fp16 HMMA): gu = X @ W13^T, h = silu(g)*u -> g_h ----------------
__global__ void __launch_bounds__(256, 1) gemm1_kernel() {
    const int e = blockIdx.z;
    const int rows = g_cnt[e];
    const int rt = blockIdx.x;
    if (rt * 128 >= rows) return;
    const int ct = blockIdx.y;     // 0..7 : g/u cols ct*64..+64
    const int base = g_off[e];

    extern __shared__ char smraw[];
    uint32_t sm = smem_u32(smraw);
    const int tid = threadIdx.x, wid = tid >> 5, lane = tid & 31;
    const int wm = wid >> 1, wn = wid & 1;

    LoadCtx c;
    {
        int r = tid >> 1;          // 0..127
        int kc0 = (tid & 1) * 4;   // first of 4 chunks
        int arow = rt * 128 + r;
        int v = arow < rows;
        int tok = v ? g_tok[e * CAP + arow] : 0;
        c.a = g_xh + (size_t)tok * HIDDEN + kc0 * 8;
        c.asz = v ? 16 : 0;
        int half = (r >> 5) & 1, wnn = r >> 6, cc = r & 31;
        int w13row = half * 512 + ct * 64 + wnn * 32 + cc;
        c.b = g_w13h + ((size_t)e * 1024 + w13row) * HIDDEN + kc0 * 8;
        #pragma unroll
        for (int j = 0; j < 4; j++)
            c.dst[j] = (uint32_t)(r * 128 + (((kc0 + j) ^ (r & 7)) << 4));
    }

    uint32_t arow[2], ar7[2], brow[4], br7[4];
    #pragma unroll
    for (int mi = 0; mi < 2; mi++) {
        uint32_t r = wm * 32 + mi * 16 + (lane & 15);
        arow[mi] = r << 7; ar7[mi] = r & 7;
    }
    #pragma unroll
    for (int q = 0; q < 4; q++) {
        uint32_t r = wn * 64 + q * 16 + (lane & 7) + ((lane >> 4) & 1) * 8;
        brow[q] = r << 7; br7[q] = r & 7;
    }

    float acc[2][8][4];
    #pragma unroll
    for (int i = 0; i < 2; i++)
        #pragma unroll
        for (int j = 0; j < 8; j++)
            #pragma unroll
            for (int q = 0; q < 4; q++) acc[i][j][q] = 0.0f;

    const int NCH = HIDDEN / 64;   // 24
    load_stage(sm, 0, 0, c);  CP_COMMIT();
    load_stage(sm, 1, 64, c); CP_COMMIT();
    for (int k = 0; k < NCH; k++) {
        CP_WAIT1();
        __syncthreads();
        if (k + 2 < NCH) load_stage(sm, (k + 2) % NST, (k + 2) * 64, c);
        CP_COMMIT();
        compute_stage(sm + (k % NST) * STAGE_B, lane, arow, ar7, brow, br7, acc);
    }

    // epilogue: ni 0..3 = g, ni+4 = u ; h = silu(g)*u -> fp16
    const int lr = lane >> 2, lc = lane & 3;
    #pragma unroll
    for (int mi = 0; mi < 2; mi++)
        #pragma unroll
        for (int half = 0; half < 2; half++) {
            int row = rt * 128 + wm * 32 + mi * 16 + lr + half * 8;
            if (row >= rows) continue;
            size_t hb = ((size_t)(base + row)) * INTER + ct * 64 + wn * 32 + lc * 2;
            #pragma unroll
            for (int ni = 0; ni < 4; ni++) {
                float g0 = acc[mi][ni][2 * half],     u0 = acc[mi][ni + 4][2 * half];
                float g1 = acc[mi][ni][2 * half + 1], u1 = acc[mi][ni + 4][2 * half + 1];
                float h0 = __fdividef(g0 * u0, 1.0f + __expf(-g0));
                float h1 = __fdividef(g1 * u1, 1.0f + __expf(-g1));
                *(__half2*)(g_h + hb + ni * 8) = __floats2half2_rn(h0, h1);
            }
        }
}

// ---------------- GEMM2 (fp16 HMMA): y = wt * (h @ W2^T) -> fp16 ----------------
__global__ void __launch_bounds__(256, 1) gemm2_kernel() {
    const int e = blockIdx.z;
    const int rows = g_cnt[e];
    const int rt = blockIdx.x;
    if (rt * 128 >= rows) return;
    const int ct = blockIdx.y;     // 0..11
    const int base = g_off[e];

    extern __shared__ char smraw[];
    uint32_t sm = smem_u32(smraw);
    const int tid = threadIdx.x, wid = tid >> 5, lane = tid & 31;
    const int wm = wid >> 1, wn = wid & 1;

    LoadCtx c;
    {
        int r = tid >> 1;
        int kc0 = (tid & 1) * 4;
        int arow = rt * 128 + r;
        int v = arow < rows;
        size_t hrow = (size_t)(base + (v ? arow : 0));
        c.a = g_h + hrow * INTER + kc0 * 8;
        c.asz = v ? 16 : 0;
        size_t brr = (size_t)e * HIDDEN + ct * 128 + r;
        c.b = g_w2h + brr * INTER + kc0 * 8;
        #pragma unroll
        for (int j = 0; j < 4; j++)
            c.dst[j] = (uint32_t)(r * 128 + (((kc0 + j) ^ (r & 7)) << 4));
    }

    uint32_t arow[2], ar7[2], brow[4], br7[4];
    #pragma unroll
    for (int mi = 0; mi < 2; mi++) {
        uint32_t r = wm * 32 + mi * 16 + (lane & 15);
        arow[mi] = r << 7; ar7[mi] = r & 7;
    }
    #pragma unroll
    for (int q = 0; q < 4; q++) {
        uint32_t r = wn * 64 + q * 16 + (lane & 7) + ((lane >> 4) & 1) * 8;
        brow[q] = r << 7; br7[q] = r & 7;
    }

    float acc[2][8][4];
    #pragma unroll
    for (int i = 0; i < 2; i++)
        #pragma unroll
        for (int j = 0; j < 8; j++)
            #pragma unroll
            for (int q = 0; q < 4; q++) acc[i][j][q] = 0.0f;

    const int NCH = INTER / 64;    // 8
    load_stage(sm, 0, 0, c);  CP_COMMIT();
    load_stage(sm, 1, 64, c); CP_COMMIT();
    for (int k = 0; k < NCH; k++) {
        CP_WAIT1();
        __syncthreads();
        if (k + 2 < NCH) load_stage(sm, (k + 2) % NST, (k + 2) * 64, c);
        CP_COMMIT();
        compute_stage(sm + (k % NST) * STAGE_B, lane, arow, ar7, brow, br7, acc);
    }

    const int lr = lane >> 2, lc = lane & 3;
    #pragma unroll
    for (int mi = 0; mi < 2; mi++)
        #pragma unroll
        for (int half = 0; half < 2; half++) {
            int row = rt * 128 + wm * 32 + mi * 16 + lr + half * 8;
            if (row >= rows) continue;
            float w = g_wt[e * CAP + row];
            __half* yp = g_y + (size_t)(base + row) * HIDDEN + ct * 128 + wn * 64 + lc * 2;
            #pragma unroll
            for (int ni = 0; ni < 8; ni++)
                *(__half2*)(yp + ni * 8) =
                    __floats2half2_rn(w * acc[mi][ni][2 * half], w * acc[mi][ni][2 * half + 1]);
        }
}

// ---------------- gather: out[t] = sum_k y[row_k] (fp32 accumulate) ----------------
__global__ void gather_kernel(float* __restrict__ out) {
    const int t = blockIdx.x;
    int rowid[TOP_K];
    #pragma unroll
    for (int k = 0; k < TOP_K; k++) {
        int pp = g_pair[t * TOP_K + k];
        rowid[k] = g_off[pp >> 20] + (pp & 0xFFFFF);
    }
    for (int cc = threadIdx.x * 8; cc < HIDDEN; cc += blockDim.x * 8) {
        float acc[8] = {};
        #pragma unroll
        for (int k = 0; k < TOP_K; k++) {
            uint4 raw = *(const uint4*)(g_y + (size_t)rowid[k] * HIDDEN + cc);
            const __half2* hp = (const __half2*)&raw;
            #pragma unroll
            for (int j = 0; j < 4; j++) {
                float2 v = __half22float2(hp[j]);
                acc[2 * j] += v.x; acc[2 * j + 1] += v.y;
            }
        }
        float4* op = (float4*)(out + (size_t)t * HIDDEN + cc);
        op[0] = make_float4(acc[0], acc[1], acc[2], acc[3]);
        op[1] = make_float4(acc[4], acc[5], acc[6], acc[7]);
    }
}

// ---------------- launch ----------------
// NOTE: order chosen so the 6th launch (ncu -s 5 -c 1) is gemm1_kernel.
extern "C" void kernel_launch(void* const* d_in, const int* in_sizes, int n_in,
                              void* d_out, int out_size) {
    const float* x      = (const float*)d_in[0];
    const float* gate_w = (const float*)d_in[1];
    const float* w13    = (const float*)d_in[2];
    const float* w2     = (const float*)d_in[3];
    float* out = (float*)d_out;

    cudaFuncSetAttribute(gemm1_kernel, cudaFuncAttributeMaxDynamicSharedMemorySize, SMEM_DYN);
    cudaFuncSetAttribute(gemm2_kernel, cudaFuncAttributeMaxDynamicSharedMemorySize, SMEM_DYN);

    __half *xh, *w13h, *w2h;
    cudaGetSymbolAddress((void**)&xh,   g_xh);
    cudaGetSymbolAddress((void**)&w13h, g_w13h);
    cudaGetSymbolAddress((void**)&w2h,  g_w2h);

    zero_cnt_kernel<<<1, 32>>>();                                                  // 1
    router_kernel<<<T_TOT, 256>>>(x, gate_w);                                      // 2
    prefix_kernel<<<1, 32>>>();                                                    // 3
    tohalf_kernel<<<2048, 256>>>(x,   xh,   (size_t)T_TOT * HIDDEN / 8);           // 4
    tohalf_kernel<<<4096, 256>>>(w13, w13h, (size_t)NUM_EXPERTS * 2 * INTER * HIDDEN / 8); // 5
    gemm1_kernel<<<dim3(T_TOT / 128, INTER / 64, NUM_EXPERTS), 256, SMEM_DYN>>>(); // 6 <- profiled
    tohalf_kernel<<<4096, 256>>>(w2,  w2h,  (size_t)NUM_EXPERTS * HIDDEN * INTER / 8);     // 7
    gemm2_kernel<<<dim3(T_TOT / 128, HIDDEN / 128, NUM_EXPERTS), 256, SMEM_DYN>>>();       // 8
    gather_kernel<<<T_TOT, 128>>>(out);                                            // 9
}

// round 8
// speedup vs baseline: 5.4468x; 1.7760x over previous
#include <cuda_runtime.h>
#include <cuda_fp16.h>
#include <cstdint>
#include <math.h>

#define NUM_EXPERTS 32
#define TOP_K 8
#define HIDDEN 1536
#define INTER 512
#define T_TOT 8192
#define CAP 8192
#define ROWS_TOT (T_TOT * TOP_K)

// ---------------- device scratch ----------------
__device__ int   g_cnt[NUM_EXPERTS];
__device__ int   g_off[NUM_EXPERTS];
__device__ int   g_tok[NUM_EXPERTS * CAP];
__device__ float g_wt [NUM_EXPERTS * CAP];
__device__ int   g_pair[T_TOT * TOP_K];
__device__ float g_logits[(size_t)T_TOT * NUM_EXPERTS];

__device__ __half g_xh[(size_t)T_TOT * HIDDEN];
__device__ __half g_w13h[(size_t)NUM_EXPERTS * 2 * INTER * HIDDEN];
__device__ __half g_w2h[(size_t)NUM_EXPERTS * HIDDEN * INTER];
__device__ __half g_h[(size_t)ROWS_TOT * INTER];
__device__ __half g_y[(size_t)ROWS_TOT * HIDDEN];

// ---------------- helpers ----------------
__device__ __forceinline__ uint32_t smem_u32(const void* p) {
    uint32_t a;
    asm("{ .reg .u64 t; cvta.to.shared.u64 t, %1; cvt.u32.u64 %0, t; }" : "=r"(a) : "l"(p));
    return a;
}
__device__ __forceinline__ void cp16(uint32_t dst, const void* src, int sz) {
    asm volatile("cp.async.cg.shared.global [%0], [%1], 16, %2;"
                 :: "r"(dst), "l"(__cvta_generic_to_global(src)), "r"(sz));
}
#define CP_COMMIT() asm volatile("cp.async.commit_group;")
#define CP_WAIT1()  asm volatile("cp.async.wait_group 1;")

__device__ __forceinline__ void ldm4(uint32_t* r, uint32_t addr) {
    asm volatile("ldmatrix.sync.aligned.m8n8.x4.shared.b16 {%0,%1,%2,%3}, [%4];"
                 : "=r"(r[0]), "=r"(r[1]), "=r"(r[2]), "=r"(r[3]) : "r"(addr));
}
__device__ __forceinline__ void mma16816(float* c, const uint32_t* a, uint32_t b0, uint32_t b1) {
    asm volatile("mma.sync.aligned.m16n8k16.row.col.f32.f16.f16.f32 "
                 "{%0,%1,%2,%3}, {%4,%5,%6,%7}, {%8,%9}, {%0,%1,%2,%3};"
                 : "+f"(c[0]), "+f"(c[1]), "+f"(c[2]), "+f"(c[3])
                 : "r"(a[0]), "r"(a[1]), "r"(a[2]), "r"(a[3]), "r"(b0), "r"(b1));
}

// smem: 2 tiles (A, B) of 128 rows x 64 fp16 = 128B/row, 16B-chunk XOR swizzle
#define TILE_B  16384
#define OFF_A   0
#define OFF_B   16384
#define STAGE_B 32768
#define NST 3
#define SMEM_DYN (NST * STAGE_B)   // 98304

struct LoadCtx {
    const __half *a, *b;
    int asz;
    uint32_t dst[4];
};

__device__ __forceinline__ void load_stage(uint32_t sm, int st, int koff, const LoadCtx& c) {
    uint32_t b = sm + st * STAGE_B;
    #pragma unroll
    for (int j = 0; j < 4; j++) {
        cp16(b + OFF_A + c.dst[j], c.a + koff + j * 8, c.asz);
        cp16(b + OFF_B + c.dst[j], c.b + koff + j * 8, 16);
    }
}

__device__ __forceinline__ void compute_stage(
        uint32_t sbase, int lane,
        const uint32_t arow[2], const uint32_t ar7[2],
        const uint32_t brow[4], const uint32_t br7[4],
        float acc[2][8][4]) {
    const uint32_t asel = lane >> 4;
    const uint32_t bsel = (lane >> 3) & 1;
    #pragma unroll
    for (int kk = 0; kk < 4; kk++) {
        uint32_t a[2][4];
        #pragma unroll
        for (int mi = 0; mi < 2; mi++) {
            uint32_t ch = kk * 2 + asel;
            ldm4(a[mi], sbase + OFF_A + arow[mi] + (((ch ^ ar7[mi]) & 7) << 4));
        }
        uint32_t b[4][4];
        #pragma unroll
        for (int q = 0; q < 4; q++) {
            uint32_t ch = kk * 2 + bsel;
            ldm4(b[q], sbase + OFF_B + brow[q] + (((ch ^ br7[q]) & 7) << 4));
        }
        #pragma unroll
        for (int ni = 0; ni < 8; ni++)
            #pragma unroll
            for (int mi = 0; mi < 2; mi++)
                mma16816(acc[mi][ni], a[mi], b[ni >> 1][2 * (ni & 1)], b[ni >> 1][2 * (ni & 1) + 1]);
    }
}

// ---------------- small kernels ----------------
__global__ void zero_cnt_kernel() {
    if (threadIdx.x < NUM_EXPERTS) g_cnt[threadIdx.x] = 0;
}
__global__ void prefix_kernel() {
    if (threadIdx.x == 0) {
        int s = 0;
        for (int e = 0; e < NUM_EXPERTS; e++) { g_off[e] = s; s += g_cnt[e]; }
    }
}
__global__ void tohalf_kernel(const float* __restrict__ src, __half* __restrict__ dst, size_t n8) {
    size_t i = (size_t)blockIdx.x * blockDim.x + threadIdx.x;
    size_t stride = (size_t)gridDim.x * blockDim.x;
    for (; i < n8; i += stride) {
        float4 v0 = __ldcs(((const float4*)src) + 2 * i);
        float4 v1 = __ldcs(((const float4*)src) + 2 * i + 1);
        uint4 o;
        __half2 h0 = __floats2half2_rn(v0.x, v0.y);
        __half2 h1 = __floats2half2_rn(v0.z, v0.w);
        __half2 h2 = __floats2half2_rn(v1.x, v1.y);
        __half2 h3 = __floats2half2_rn(v1.z, v1.w);
        o.x = *(uint32_t*)&h0; o.y = *(uint32_t*)&h1;
        o.z = *(uint32_t*)&h2; o.w = *(uint32_t*)&h3;
        ((uint4*)dst)[i] = o;
    }
}

// ---------------- router stage 1: logits = x @ gate_w^T (fp32, tiled) ----------------
// grid 64 (128 tokens each), block 256. smem: xs[k][tok] (129-pad) + gs[k][e] (33-pad)
#define RXS 129
#define RGS 33
#define R_SMEM ((128 * RXS + 128 * RGS) * 4)   // 82944 B
__global__ void __launch_bounds__(256) router_logits_kernel(
        const float* __restrict__ x, const float* __restrict__ gate_w) {
    extern __shared__ float rsm[];
    float* xs = rsm;                // [k*RXS + tok]
    float* gs = rsm + 128 * RXS;    // [k*RGS + e]
    const int tid = threadIdx.x, lane = tid & 31;
    const int t0 = blockIdx.x * 128;
    const int e0 = (tid >> 5) * 4;

    float acc[4][4];
    #pragma unroll
    for (int i = 0; i < 4; i++)
        #pragma unroll
        for (int j = 0; j < 4; j++) acc[i][j] = 0.0f;

    for (int ch = 0; ch < HIDDEN / 128; ch++) {
        __syncthreads();
        // x chunk: 128 tok x 128 k = 4096 float4; kq=i&31, tok=i>>5 (coalesced LDG)
        for (int i = tid; i < 4096; i += 256) {
            int tok = i >> 5, kq = i & 31;
            float4 v = *(const float4*)&x[(size_t)(t0 + tok) * HIDDEN + ch * 128 + kq * 4];
            xs[(4 * kq + 0) * RXS + tok] = v.x;
            xs[(4 * kq + 1) * RXS + tok] = v.y;
            xs[(4 * kq + 2) * RXS + tok] = v.z;
            xs[(4 * kq + 3) * RXS + tok] = v.w;
        }
        // gate chunk: 32 e x 128 k = 1024 float4
        for (int i = tid; i < 1024; i += 256) {
            int e = i >> 5, kq = i & 31;
            float4 v = *(const float4*)&gate_w[(size_t)e * HIDDEN + ch * 128 + kq * 4];
            gs[(4 * kq + 0) * RGS + e] = v.x;
            gs[(4 * kq + 1) * RGS + e] = v.y;
            gs[(4 * kq + 2) * RGS + e] = v.z;
            gs[(4 * kq + 3) * RGS + e] = v.w;
        }
        __syncthreads();
        #pragma unroll 4
        for (int kk = 0; kk < 128; kk++) {
            float gg[4];
            #pragma unroll
            for (int j = 0; j < 4; j++) gg[j] = gs[kk * RGS + e0 + j];
            #pragma unroll
            for (int i = 0; i < 4; i++) {
                float xv = xs[kk * RXS + lane + 32 * i];
                #pragma unroll
                for (int j = 0; j < 4; j++) acc[i][j] = fmaf(xv, gg[j], acc[i][j]);
            }
        }
    }
    #pragma unroll
    for (int i = 0; i < 4; i++)
        #pragma unroll
        for (int j = 0; j < 4; j++)
            g_logits[(size_t)(t0 + lane + 32 * i) * NUM_EXPERTS + e0 + j] = acc[i][j];
}

// ---------------- router stage 2: top-8 + scatter ----------------
__global__ void topk_kernel() {
    const int t = blockIdx.x * blockDim.x + threadIdx.x;
    if (t >= T_TOT) return;
    float lg[NUM_EXPERTS];
    #pragma unroll
    for (int q = 0; q < 8; q++) {
        float4 v = *(const float4*)&g_logits[(size_t)t * NUM_EXPERTS + q * 4];
        lg[4 * q] = v.x; lg[4 * q + 1] = v.y; lg[4 * q + 2] = v.z; lg[4 * q + 3] = v.w;
    }
    float mx = -INFINITY;
    #pragma unroll
    for (int i = 0; i < NUM_EXPERTS; i++) mx = fmaxf(mx, lg[i]);
    float pr[NUM_EXPERTS];
    #pragma unroll
    for (int i = 0; i < NUM_EXPERTS; i++) pr[i] = expf(lg[i] - mx);
    int idx[TOP_K]; float w[TOP_K]; float ws = 0.0f;
    unsigned used = 0u;
    #pragma unroll
    for (int k = 0; k < TOP_K; k++) {
        int bi = -1; float bv = -INFINITY;
        #pragma unroll
        for (int i = 0; i < NUM_EXPERTS; i++)
            if (!(used >> i & 1u) && pr[i] > bv) { bv = pr[i]; bi = i; }
        used |= 1u << bi; idx[k] = bi; w[k] = bv; ws += bv;
    }
    float inv = 1.0f / ws;
    #pragma unroll
    for (int k = 0; k < TOP_K; k++) {
        int slot = atomicAdd(&g_cnt[idx[k]], 1);
        g_tok[idx[k] * CAP + slot] = t;
        g_wt [idx[k] * CAP + slot] = w[k] * inv;
        g_pair[t * TOP_K + k] = (idx[k] << 20) | slot;
    }
}

// ---------------- GEMM1 (fp16 HMMA): gu = X @ W13^T, h = silu(g)*u -> g_h ----------------
__global__ void __launch_bounds__(256, 1) gemm1_kernel() {
    const int e = blockIdx.z;
    const int rows = g_cnt[e];
    const int rt = blockIdx.x;
    if (rt * 128 >= rows) return;
    const int ct = blockIdx.y;
    const int base = g_off[e];

    extern __shared__ char smraw[];
    uint32_t sm = smem_u32(smraw);
    const int tid = threadIdx.x, wid = tid >> 5, lane = tid & 31;
    const int wm = wid >> 1, wn = wid & 1;

    LoadCtx c;
    {
        int r = tid >> 1;
        int kc0 = (tid & 1) * 4;
        int arow = rt * 128 + r;
        int v = arow < rows;
        int tok = v ? g_tok[e * CAP + arow] : 0;
        c.a = g_xh + (size_t)tok * HIDDEN + kc0 * 8;
        c.asz = v ? 16 : 0;
        int half = (r >> 5) & 1, wnn = r >> 6, cc = r & 31;
        int w13row = half * 512 + ct * 64 + wnn * 32 + cc;
        c.b = g_w13h + ((size_t)e * 1024 + w13row) * HIDDEN + kc0 * 8;
        #pragma unroll
        for (int j = 0; j < 4; j++)
            c.dst[j] = (uint32_t)(r * 128 + (((kc0 + j) ^ (r & 7)) << 4));
    }

    uint32_t arow[2], ar7[2], brow[4], br7[4];
    #pragma unroll
    for (int mi = 0; mi < 2; mi++) {
        uint32_t r = wm * 32 + mi * 16 + (lane & 15);
        arow[mi] = r << 7; ar7[mi] = r & 7;
    }
    #pragma unroll
    for (int q = 0; q < 4; q++) {
        uint32_t r = wn * 64 + q * 16 + (lane & 7) + ((lane >> 4) & 1) * 8;
        brow[q] = r << 7; br7[q] = r & 7;
    }

    float acc[2][8][4];
    #pragma unroll
    for (int i = 0; i < 2; i++)
        #pragma unroll
        for (int j = 0; j < 8; j++)
            #pragma unroll
            for (int q = 0; q < 4; q++) acc[i][j][q] = 0.0f;

    const int NCH = HIDDEN / 64;
    load_stage(sm, 0, 0, c);  CP_COMMIT();
    load_stage(sm, 1, 64, c); CP_COMMIT();
    for (int k = 0; k < NCH; k++) {
        CP_WAIT1();
        __syncthreads();
        if (k + 2 < NCH) load_stage(sm, (k + 2) % NST, (k + 2) * 64, c);
        CP_COMMIT();
        compute_stage(sm + (k % NST) * STAGE_B, lane, arow, ar7, brow, br7, acc);
    }

    const int lr = lane >> 2, lc = lane & 3;
    #pragma unroll
    for (int mi = 0; mi < 2; mi++)
        #pragma unroll
        for (int half = 0; half < 2; half++) {
            int row = rt * 128 + wm * 32 + mi * 16 + lr + half * 8;
            if (row >= rows) continue;
            size_t hb = ((size_t)(base + row)) * INTER + ct * 64 + wn * 32 + lc * 2;
            #pragma unroll
            for (int ni = 0; ni < 4; ni++) {
                float g0 = acc[mi][ni][2 * half],     u0 = acc[mi][ni + 4][2 * half];
                float g1 = acc[mi][ni][2 * half + 1], u1 = acc[mi][ni + 4][2 * half + 1];
                float h0 = __fdividef(g0 * u0, 1.0f + __expf(-g0));
                float h1 = __fdividef(g1 * u1, 1.0f + __expf(-g1));
                *(__half2*)(g_h + hb + ni * 8) = __floats2half2_rn(h0, h1);
            }
        }
}

// ---------------- GEMM2 (fp16 HMMA): y = wt * (h @ W2^T) -> fp16 ----------------
__global__ void __launch_bounds__(256, 1) gemm2_kernel() {
    const int e = blockIdx.z;
    const int rows = g_cnt[e];
    const int rt = blockIdx.x;
    if (rt * 128 >= rows) return;
    const int ct = blockIdx.y;
    const int base = g_off[e];

    extern __shared__ char smraw[];
    uint32_t sm = smem_u32(smraw);
    const int tid = threadIdx.x, wid = tid >> 5, lane = tid & 31;
    const int wm = wid >> 1, wn = wid & 1;

    LoadCtx c;
    {
        int r = tid >> 1;
        int kc0 = (tid & 1) * 4;
        int arow = rt * 128 + r;
        int v = arow < rows;
        size_t hrow = (size_t)(base + (v ? arow : 0));
        c.a = g_h + hrow * INTER + kc0 * 8;
        c.asz = v ? 16 : 0;
        size_t brr = (size_t)e * HIDDEN + ct * 128 + r;
        c.b = g_w2h + brr * INTER + kc0 * 8;
        #pragma unroll
        for (int j = 0; j < 4; j++)
            c.dst[j] = (uint32_t)(r * 128 + (((kc0 + j) ^ (r & 7)) << 4));
    }

    uint32_t arow[2], ar7[2], brow[4], br7[4];
    #pragma unroll
    for (int mi = 0; mi < 2; mi++) {
        uint32_t r = wm * 32 + mi * 16 + (lane & 15);
        arow[mi] = r << 7; ar7[mi] = r & 7;
    }
    #pragma unroll
    for (int q = 0; q < 4; q++) {
        uint32_t r = wn * 64 + q * 16 + (lane & 7) + ((lane >> 4) & 1) * 8;
        brow[q] = r << 7; br7[q] = r & 7;
    }

    float acc[2][8][4];
    #pragma unroll
    for (int i = 0; i < 2; i++)
        #pragma unroll
        for (int j = 0; j < 8; j++)
            #pragma unroll
            for (int q = 0; q < 4; q++) acc[i][j][q] = 0.0f;

    const int NCH = INTER / 64;
    load_stage(sm, 0, 0, c);  CP_COMMIT();
    load_stage(sm, 1, 64, c); CP_COMMIT();
    for (int k = 0; k < NCH; k++) {
        CP_WAIT1();
        __syncthreads();
        if (k + 2 < NCH) load_stage(sm, (k + 2) % NST, (k + 2) * 64, c);
        CP_COMMIT();
        compute_stage(sm + (k % NST) * STAGE_B, lane, arow, ar7, brow, br7, acc);
    }

    const int lr = lane >> 2, lc = lane & 3;
    #pragma unroll
    for (int mi = 0; mi < 2; mi++)
        #pragma unroll
        for (int half = 0; half < 2; half++) {
            int row = rt * 128 + wm * 32 + mi * 16 + lr + half * 8;
            if (row >= rows) continue;
            float w = g_wt[e * CAP + row];
            __half* yp = g_y + (size_t)(base + row) * HIDDEN + ct * 128 + wn * 64 + lc * 2;
            #pragma unroll
            for (int ni = 0; ni < 8; ni++)
                *(__half2*)(yp + ni * 8) =
                    __floats2half2_rn(w * acc[mi][ni][2 * half], w * acc[mi][ni][2 * half + 1]);
        }
}

// ---------------- gather ----------------
__global__ void gather_kernel(float* __restrict__ out) {
    const int t = blockIdx.x;
    int rowid[TOP_K];
    #pragma unroll
    for (int k = 0; k < TOP_K; k++) {
        int pp = g_pair[t * TOP_K + k];
        rowid[k] = g_off[pp >> 20] + (pp & 0xFFFFF);
    }
    for (int cc = threadIdx.x * 8; cc < HIDDEN; cc += blockDim.x * 8) {
        float acc[8] = {};
        #pragma unroll
        for (int k = 0; k < TOP_K; k++) {
            uint4 raw = *(const uint4*)(g_y + (size_t)rowid[k] * HIDDEN + cc);
            const __half2* hp = (const __half2*)&raw;
            #pragma unroll
            for (int j = 0; j < 4; j++) {
                float2 v = __half22float2(hp[j]);
                acc[2 * j] += v.x; acc[2 * j + 1] += v.y;
            }
        }
        float4* op = (float4*)(out + (size_t)t * HIDDEN + cc);
        op[0] = make_float4(acc[0], acc[1], acc[2], acc[3]);
        op[1] = make_float4(acc[4], acc[5], acc[6], acc[7]);
    }
}

// ---------------- launch (stream-forked prologue) ----------------
extern "C" void kernel_launch(void* const* d_in, const int* in_sizes, int n_in,
                              void* d_out, int out_size) {
    const float* x      = (const float*)d_in[0];
    const float* gate_w = (const float*)d_in[1];
    const float* w13    = (const float*)d_in[2];
    const float* w2     = (const float*)d_in[3];
    float* out = (float*)d_out;

    static bool init = false;
    static cudaStream_t s1, s2;
    static cudaEvent_t ev0, ev1, ev2;
    if (!init) {
        cudaStreamCreateWithFlags(&s1, cudaStreamNonBlocking);
        cudaStreamCreateWithFlags(&s2, cudaStreamNonBlocking);
        cudaEventCreateWithFlags(&ev0, cudaEventDisableTiming);
        cudaEventCreateWithFlags(&ev1, cudaEventDisableTiming);
        cudaEventCreateWithFlags(&ev2, cudaEventDisableTiming);
        cudaFuncSetAttribute(gemm1_kernel, cudaFuncAttributeMaxDynamicSharedMemorySize, SMEM_DYN);
        cudaFuncSetAttribute(gemm2_kernel, cudaFuncAttributeMaxDynamicSharedMemorySize, SMEM_DYN);
        cudaFuncSetAttribute(router_logits_kernel, cudaFuncAttributeMaxDynamicSharedMemorySize, R_SMEM);
        init = true;
    }

    __half *xh, *w13h, *w2h;
    cudaGetSymbolAddress((void**)&xh,   g_xh);
    cudaGetSymbolAddress((void**)&w13h, g_w13h);
    cudaGetSymbolAddress((void**)&w2h,  g_w2h);

    // fork
    cudaEventRecord(ev0, 0);
    cudaStreamWaitEvent(s1, ev0, 0);
    cudaStreamWaitEvent(s2, ev0, 0);

    // main: router path
    zero_cnt_kernel<<<1, 32>>>();
    router_logits_kernel<<<T_TOT / 128, 256, R_SMEM>>>(x, gate_w);
    topk_kernel<<<T_TOT / 256, 256>>>();
    prefix_kernel<<<1, 32>>>();

    // s1: conversions needed by gemm1
    tohalf_kernel<<<2048, 256, 0, s1>>>(x,   xh,   (size_t)T_TOT * HIDDEN / 8);
    tohalf_kernel<<<4096, 256, 0, s1>>>(w13, w13h, (size_t)NUM_EXPERTS * 2 * INTER * HIDDEN / 8);
    // s2: conversion needed only by gemm2 (hides under gemm1)
    tohalf_kernel<<<4096, 256, 0, s2>>>(w2,  w2h,  (size_t)NUM_EXPERTS * HIDDEN * INTER / 8);

    // join s1 before gemm1
    cudaEventRecord(ev1, s1);
    cudaStreamWaitEvent(0, ev1, 0);
    gemm1_kernel<<<dim3(T_TOT / 128, INTER / 64, NUM_EXPERTS), 256, SMEM_DYN>>>();

    // join s2 before gemm2
    cudaEventRecord(ev2, s2);
    cudaStreamWaitEvent(0, ev2, 0);
    gemm2_kernel<<<dim3(T_TOT / 128, HIDDEN / 128, NUM_EXPERTS), 256, SMEM_DYN>>>();

    gather_kernel<<<T_TOT, 128>>>(out);
}

// round 9
// speedup vs baseline: 6.7818x; 1.2451x over previous
#include <cuda_runtime.h>
#include <cuda_fp16.h>
#include <cstdint>
#include <math.h>

#define NUM_EXPERTS 32
#define TOP_K 8
#define HIDDEN 1536
#define INTER 512
#define T_TOT 8192
#define CAP 8192
#define ROWS_TOT (T_TOT * TOP_K)

// ---------------- device scratch ----------------
__device__ int   g_cnt[NUM_EXPERTS];
__device__ int   g_off[NUM_EXPERTS];
__device__ int   g_tok[NUM_EXPERTS * CAP];
__device__ float g_wt [NUM_EXPERTS * CAP];
__device__ int   g_pair[T_TOT * TOP_K];
__device__ float g_logits[(size_t)T_TOT * NUM_EXPERTS];

__device__ __half g_xh[(size_t)T_TOT * HIDDEN];
__device__ __half g_w13h[(size_t)NUM_EXPERTS * 2 * INTER * HIDDEN];
__device__ __half g_w2h[(size_t)NUM_EXPERTS * HIDDEN * INTER];
__device__ __half g_h[(size_t)ROWS_TOT * INTER];
__device__ __half g_y[(size_t)ROWS_TOT * HIDDEN];

// ---------------- helpers ----------------
__device__ __forceinline__ uint32_t smem_u32(const void* p) {
    uint32_t a;
    asm("{ .reg .u64 t; cvta.to.shared.u64 t, %1; cvt.u32.u64 %0, t; }" : "=r"(a) : "l"(p));
    return a;
}
__device__ __forceinline__ void cp16(uint32_t dst, const void* src, int sz) {
    asm volatile("cp.async.cg.shared.global [%0], [%1], 16, %2;"
                 :: "r"(dst), "l"(__cvta_generic_to_global(src)), "r"(sz));
}
#define CP_COMMIT() asm volatile("cp.async.commit_group;")
#define CP_WAIT1()  asm volatile("cp.async.wait_group 1;")

__device__ __forceinline__ void ldm4(uint32_t* r, uint32_t addr) {
    asm volatile("ldmatrix.sync.aligned.m8n8.x4.shared.b16 {%0,%1,%2,%3}, [%4];"
                 : "=r"(r[0]), "=r"(r[1]), "=r"(r[2]), "=r"(r[3]) : "r"(addr));
}
__device__ __forceinline__ void mma16816(float* c, const uint32_t* a, uint32_t b0, uint32_t b1) {
    asm volatile("mma.sync.aligned.m16n8k16.row.col.f32.f16.f16.f32 "
                 "{%0,%1,%2,%3}, {%4,%5,%6,%7}, {%8,%9}, {%0,%1,%2,%3};"
                 : "+f"(c[0]), "+f"(c[1]), "+f"(c[2]), "+f"(c[3])
                 : "r"(a[0]), "r"(a[1]), "r"(a[2]), "r"(a[3]), "r"(b0), "r"(b1));
}

// smem: 2 tiles (A, B) of 128 rows x 64 fp16 = 128B/row, 16B-chunk XOR swizzle
#define TILE_B  16384
#define OFF_A   0
#define OFF_B   16384
#define STAGE_B 32768
#define NST 3
#define SMEM_DYN (NST * STAGE_B)   // 98304 -> 2 CTAs/SM = 192KB <= 228KB

struct LoadCtx {
    const __half *a, *b;
    int asz;
    uint32_t dst[4];
};

__device__ __forceinline__ void load_stage(uint32_t sm, int st, int koff, const LoadCtx& c) {
    uint32_t b = sm + st * STAGE_B;
    #pragma unroll
    for (int j = 0; j < 4; j++) {
        cp16(b + OFF_A + c.dst[j], c.a + koff + j * 8, c.asz);
        cp16(b + OFF_B + c.dst[j], c.b + koff + j * 8, 16);
    }
}

__device__ __forceinline__ void compute_stage(
        uint32_t sbase, int lane,
        const uint32_t arow[2], const uint32_t ar7[2],
        const uint32_t brow[4], const uint32_t br7[4],
        float acc[2][8][4]) {
    const uint32_t asel = lane >> 4;
    const uint32_t bsel = (lane >> 3) & 1;
    #pragma unroll
    for (int kk = 0; kk < 4; kk++) {
        uint32_t a[2][4];
        #pragma unroll
        for (int mi = 0; mi < 2; mi++) {
            uint32_t ch = kk * 2 + asel;
            ldm4(a[mi], sbase + OFF_A + arow[mi] + (((ch ^ ar7[mi]) & 7) << 4));
        }
        uint32_t b[4][4];
        #pragma unroll
        for (int q = 0; q < 4; q++) {
            uint32_t ch = kk * 2 + bsel;
            ldm4(b[q], sbase + OFF_B + brow[q] + (((ch ^ br7[q]) & 7) << 4));
        }
        #pragma unroll
        for (int ni = 0; ni < 8; ni++)
            #pragma unroll
            for (int mi = 0; mi < 2; mi++)
                mma16816(acc[mi][ni], a[mi], b[ni >> 1][2 * (ni & 1)], b[ni >> 1][2 * (ni & 1) + 1]);
    }
}

// ---------------- small kernels ----------------
__global__ void prefix_kernel() {
    if (threadIdx.x == 0) {
        int s = 0;
        for (int e = 0; e < NUM_EXPERTS; e++) { g_off[e] = s; s += g_cnt[e]; }
    }
}
__global__ void tohalf_kernel(const float* __restrict__ src, __half* __restrict__ dst, size_t n8) {
    size_t i = (size_t)blockIdx.x * blockDim.x + threadIdx.x;
    size_t stride = (size_t)gridDim.x * blockDim.x;
    for (; i < n8; i += stride) {
        float4 v0 = __ldcs(((const float4*)src) + 2 * i);
        float4 v1 = __ldcs(((const float4*)src) + 2 * i + 1);
        uint4 o;
        __half2 h0 = __floats2half2_rn(v0.x, v0.y);
        __half2 h1 = __floats2half2_rn(v0.z, v0.w);
        __half2 h2 = __floats2half2_rn(v1.x, v1.y);
        __half2 h3 = __floats2half2_rn(v1.z, v1.w);
        o.x = *(uint32_t*)&h0; o.y = *(uint32_t*)&h1;
        o.z = *(uint32_t*)&h2; o.w = *(uint32_t*)&h3;
        ((uint4*)dst)[i] = o;
    }
}

// ---------------- router stage 1: logits = x @ gate_w^T (fp32, tiled) ----------------
#define RXS 129
#define RGS 33
#define R_SMEM ((128 * RXS + 128 * RGS) * 4)   // 82944 B
__global__ void __launch_bounds__(256) router_logits_kernel(
        const float* __restrict__ x, const float* __restrict__ gate_w) {
    extern __shared__ float rsm[];
    float* xs = rsm;
    float* gs = rsm + 128 * RXS;
    const int tid = threadIdx.x, lane = tid & 31;
    const int t0 = blockIdx.x * 128;
    const int e0 = (tid >> 5) * 4;

    if (blockIdx.x == 0 && tid < NUM_EXPERTS) g_cnt[tid] = 0;  // fused zero

    float acc[4][4];
    #pragma unroll
    for (int i = 0; i < 4; i++)
        #pragma unroll
        for (int j = 0; j < 4; j++) acc[i][j] = 0.0f;

    for (int ch = 0; ch < HIDDEN / 128; ch++) {
        __syncthreads();
        for (int i = tid; i < 4096; i += 256) {
            int tok = i >> 5, kq = i & 31;
            float4 v = *(const float4*)&x[(size_t)(t0 + tok) * HIDDEN + ch * 128 + kq * 4];
            xs[(4 * kq + 0) * RXS + tok] = v.x;
            xs[(4 * kq + 1) * RXS + tok] = v.y;
            xs[(4 * kq + 2) * RXS + tok] = v.z;
            xs[(4 * kq + 3) * RXS + tok] = v.w;
        }
        for (int i = tid; i < 1024; i += 256) {
            int e = i >> 5, kq = i & 31;
            float4 v = *(const float4*)&gate_w[(size_t)e * HIDDEN + ch * 128 + kq * 4];
            gs[(4 * kq + 0) * RGS + e] = v.x;
            gs[(4 * kq + 1) * RGS + e] = v.y;
            gs[(4 * kq + 2) * RGS + e] = v.z;
            gs[(4 * kq + 3) * RGS + e] = v.w;
        }
        __syncthreads();
        #pragma unroll 4
        for (int kk = 0; kk < 128; kk++) {
            float gg[4];
            #pragma unroll
            for (int j = 0; j < 4; j++) gg[j] = gs[kk * RGS + e0 + j];
            #pragma unroll
            for (int i = 0; i < 4; i++) {
                float xv = xs[kk * RXS + lane + 32 * i];
                #pragma unroll
                for (int j = 0; j < 4; j++) acc[i][j] = fmaf(xv, gg[j], acc[i][j]);
            }
        }
    }
    #pragma unroll
    for (int i = 0; i < 4; i++)
        #pragma unroll
        for (int j = 0; j < 4; j++)
            g_logits[(size_t)(t0 + lane + 32 * i) * NUM_EXPERTS + e0 + j] = acc[i][j];
}

// ---------------- router stage 2: top-8 + scatter ----------------
__global__ void topk_kernel() {
    const int t = blockIdx.x * blockDim.x + threadIdx.x;
    if (t >= T_TOT) return;
    float lg[NUM_EXPERTS];
    #pragma unroll
    for (int q = 0; q < 8; q++) {
        float4 v = *(const float4*)&g_logits[(size_t)t * NUM_EXPERTS + q * 4];
        lg[4 * q] = v.x; lg[4 * q + 1] = v.y; lg[4 * q + 2] = v.z; lg[4 * q + 3] = v.w;
    }
    float mx = -INFINITY;
    #pragma unroll
    for (int i = 0; i < NUM_EXPERTS; i++) mx = fmaxf(mx, lg[i]);
    float pr[NUM_EXPERTS];
    #pragma unroll
    for (int i = 0; i < NUM_EXPERTS; i++) pr[i] = expf(lg[i] - mx);
    int idx[TOP_K]; float w[TOP_K]; float ws = 0.0f;
    unsigned used = 0u;
    #pragma unroll
    for (int k = 0; k < TOP_K; k++) {
        int bi = -1; float bv = -INFINITY;
        #pragma unroll
        for (int i = 0; i < NUM_EXPERTS; i++)
            if (!(used >> i & 1u) && pr[i] > bv) { bv = pr[i]; bi = i; }
        used |= 1u << bi; idx[k] = bi; w[k] = bv; ws += bv;
    }
    float inv = 1.0f / ws;
    #pragma unroll
    for (int k = 0; k < TOP_K; k++) {
        int slot = atomicAdd(&g_cnt[idx[k]], 1);
        g_tok[idx[k] * CAP + slot] = t;
        g_wt [idx[k] * CAP + slot] = w[k] * inv;
        g_pair[t * TOP_K + k] = (idx[k] << 20) | slot;
    }
}

// ---------------- GEMM1 (fp16 HMMA): gu = X @ W13^T, h = silu(g)*u -> g_h ----------------
__global__ void __launch_bounds__(256, 2) gemm1_kernel() {
    const int e = blockIdx.z;
    const int rows = g_cnt[e];
    const int rt = blockIdx.x;
    if (rt * 128 >= rows) return;
    const int ct = blockIdx.y;
    const int base = g_off[e];

    extern __shared__ char smraw[];
    uint32_t sm = smem_u32(smraw);
    const int tid = threadIdx.x, wid = tid >> 5, lane = tid & 31;
    const int wm = wid >> 1, wn = wid & 1;

    LoadCtx c;
    {
        int r = tid >> 1;
        int kc0 = (tid & 1) * 4;
        int arow = rt * 128 + r;
        int v = arow < rows;
        int tok = v ? g_tok[e * CAP + arow] : 0;
        c.a = g_xh + (size_t)tok * HIDDEN + kc0 * 8;
        c.asz = v ? 16 : 0;
        int half = (r >> 5) & 1, wnn = r >> 6, cc = r & 31;
        int w13row = half * 512 + ct * 64 + wnn * 32 + cc;
        c.b = g_w13h + ((size_t)e * 1024 + w13row) * HIDDEN + kc0 * 8;
        #pragma unroll
        for (int j = 0; j < 4; j++)
            c.dst[j] = (uint32_t)(r * 128 + (((kc0 + j) ^ (r & 7)) << 4));
    }

    uint32_t arow[2], ar7[2], brow[4], br7[4];
    #pragma unroll
    for (int mi = 0; mi < 2; mi++) {
        uint32_t r = wm * 32 + mi * 16 + (lane & 15);
        arow[mi] = r << 7; ar7[mi] = r & 7;
    }
    #pragma unroll
    for (int q = 0; q < 4; q++) {
        uint32_t r = wn * 64 + q * 16 + (lane & 7) + ((lane >> 4) & 1) * 8;
        brow[q] = r << 7; br7[q] = r & 7;
    }

    float acc[2][8][4];
    #pragma unroll
    for (int i = 0; i < 2; i++)
        #pragma unroll
        for (int j = 0; j < 8; j++)
            #pragma unroll
            for (int q = 0; q < 4; q++) acc[i][j][q] = 0.0f;

    const int NCH = HIDDEN / 64;
    load_stage(sm, 0, 0, c);  CP_COMMIT();
    load_stage(sm, 1, 64, c); CP_COMMIT();
    for (int k = 0; k < NCH; k++) {
        CP_WAIT1();
        __syncthreads();
        if (k + 2 < NCH) load_stage(sm, (k + 2) % NST, (k + 2) * 64, c);
        CP_COMMIT();
        compute_stage(sm + (k % NST) * STAGE_B, lane, arow, ar7, brow, br7, acc);
    }

    const int lr = lane >> 2, lc = lane & 3;
    #pragma unroll
    for (int mi = 0; mi < 2; mi++)
        #pragma unroll
        for (int half = 0; half < 2; half++) {
            int row = rt * 128 + wm * 32 + mi * 16 + lr + half * 8;
            if (row >= rows) continue;
            size_t hb = ((size_t)(base + row)) * INTER + ct * 64 + wn * 32 + lc * 2;
            #pragma unroll
            for (int ni = 0; ni < 4; ni++) {
                float g0 = acc[mi][ni][2 * half],     u0 = acc[mi][ni + 4][2 * half];
                float g1 = acc[mi][ni][2 * half + 1], u1 = acc[mi][ni + 4][2 * half + 1];
                float h0 = __fdividef(g0 * u0, 1.0f + __expf(-g0));
                float h1 = __fdividef(g1 * u1, 1.0f + __expf(-g1));
                *(__half2*)(g_h + hb + ni * 8) = __floats2half2_rn(h0, h1);
            }
        }
}

// ---------------- GEMM2 (fp16 HMMA): y = wt * (h @ W2^T) -> fp16 ----------------
__global__ void __launch_bounds__(256, 2) gemm2_kernel() {
    const int e = blockIdx.z;
    const int rows = g_cnt[e];
    const int rt = blockIdx.x;
    if (rt * 128 >= rows) return;
    const int ct = blockIdx.y;
    const int base = g_off[e];

    extern __shared__ char smraw[];
    uint32_t sm = smem_u32(smraw);
    const int tid = threadIdx.x, wid = tid >> 5, lane = tid & 31;
    const int wm = wid >> 1, wn = wid & 1;

    LoadCtx c;
    {
        int r = tid >> 1;
        int kc0 = (tid & 1) * 4;
        int arow = rt * 128 + r;
        int v = arow < rows;
        size_t hrow = (size_t)(base + (v ? arow : 0));
        c.a = g_h + hrow * INTER + kc0 * 8;
        c.asz = v ? 16 : 0;
        size_t brr = (size_t)e * HIDDEN + ct * 128 + r;
        c.b = g_w2h + brr * INTER + kc0 * 8;
        #pragma unroll
        for (int j = 0; j < 4; j++)
            c.dst[j] = (uint32_t)(r * 128 + (((kc0 + j) ^ (r & 7)) << 4));
    }

    uint32_t arow[2], ar7[2], brow[4], br7[4];
    #pragma unroll
    for (int mi = 0; mi < 2; mi++) {
        uint32_t r = wm * 32 + mi * 16 + (lane & 15);
        arow[mi] = r << 7; ar7[mi] = r & 7;
    }
    #pragma unroll
    for (int q = 0; q < 4; q++) {
        uint32_t r = wn * 64 + q * 16 + (lane & 7) + ((lane >> 4) & 1) * 8;
        brow[q] = r << 7; br7[q] = r & 7;
    }

    float acc[2][8][4];
    #pragma unroll
    for (int i = 0; i < 2; i++)
        #pragma unroll
        for (int j = 0; j < 8; j++)
            #pragma unroll
            for (int q = 0; q < 4; q++) acc[i][j][q] = 0.0f;

    const int NCH = INTER / 64;
    load_stage(sm, 0, 0, c);  CP_COMMIT();
    load_stage(sm, 1, 64, c); CP_COMMIT();
    for (int k = 0; k < NCH; k++) {
        CP_WAIT1();
        __syncthreads();
        if (k + 2 < NCH) load_stage(sm, (k + 2) % NST, (k + 2) * 64, c);
        CP_COMMIT();
        compute_stage(sm + (k % NST) * STAGE_B, lane, arow, ar7, brow, br7, acc);
    }

    const int lr = lane >> 2, lc = lane & 3;
    #pragma unroll
    for (int mi = 0; mi < 2; mi++)
        #pragma unroll
        for (int half = 0; half < 2; half++) {
            int row = rt * 128 + wm * 32 + mi * 16 + lr + half * 8;
            if (row >= rows) continue;
            float w = g_wt[e * CAP + row];
            __half* yp = g_y + (size_t)(base + row) * HIDDEN + ct * 128 + wn * 64 + lc * 2;
            #pragma unroll
            for (int ni = 0; ni < 8; ni++)
                *(__half2*)(yp + ni * 8) =
                    __floats2half2_rn(w * acc[mi][ni][2 * half], w * acc[mi][ni][2 * half + 1]);
        }
}

// ---------------- gather ----------------
__global__ void gather_kernel(float* __restrict__ out) {
    const int t = blockIdx.x;
    int rowid[TOP_K];
    #pragma unroll
    for (int k = 0; k < TOP_K; k++) {
        int pp = g_pair[t * TOP_K + k];
        rowid[k] = g_off[pp >> 20] + (pp & 0xFFFFF);
    }
    for (int cc = threadIdx.x * 8; cc < HIDDEN; cc += blockDim.x * 8) {
        float acc[8] = {};
        #pragma unroll
        for (int k = 0; k < TOP_K; k++) {
            uint4 raw = *(const uint4*)(g_y + (size_t)rowid[k] * HIDDEN + cc);
            const __half2* hp = (const __half2*)&raw;
            #pragma unroll
            for (int j = 0; j < 4; j++) {
                float2 v = __half22float2(hp[j]);
                acc[2 * j] += v.x; acc[2 * j + 1] += v.y;
            }
        }
        float4* op = (float4*)(out + (size_t)t * HIDDEN + cc);
        op[0] = make_float4(acc[0], acc[1], acc[2], acc[3]);
        op[1] = make_float4(acc[4], acc[5], acc[6], acc[7]);
    }
}

// ---------------- launch (stream-forked prologue) ----------------
extern "C" void kernel_launch(void* const* d_in, const int* in_sizes, int n_in,
                              void* d_out, int out_size) {
    const float* x      = (const float*)d_in[0];
    const float* gate_w = (const float*)d_in[1];
    const float* w13    = (const float*)d_in[2];
    const float* w2     = (const float*)d_in[3];
    float* out = (float*)d_out;

    static bool init = false;
    static cudaStream_t s1, s2;
    static cudaEvent_t ev0, ev1, ev2;
    if (!init) {
        cudaStreamCreateWithFlags(&s1, cudaStreamNonBlocking);
        cudaStreamCreateWithFlags(&s2, cudaStreamNonBlocking);
        cudaEventCreateWithFlags(&ev0, cudaEventDisableTiming);
        cudaEventCreateWithFlags(&ev1, cudaEventDisableTiming);
        cudaEventCreateWithFlags(&ev2, cudaEventDisableTiming);
        cudaFuncSetAttribute(gemm1_kernel, cudaFuncAttributeMaxDynamicSharedMemorySize, SMEM_DYN);
        cudaFuncSetAttribute(gemm2_kernel, cudaFuncAttributeMaxDynamicSharedMemorySize, SMEM_DYN);
        cudaFuncSetAttribute(router_logits_kernel, cudaFuncAttributeMaxDynamicSharedMemorySize, R_SMEM);
        init = true;
    }

    __half *xh, *w13h, *w2h;
    cudaGetSymbolAddress((void**)&xh,   g_xh);
    cudaGetSymbolAddress((void**)&w13h, g_w13h);
    cudaGetSymbolAddress((void**)&w2h,  g_w2h);

    // fork
    cudaEventRecord(ev0, 0);
    cudaStreamWaitEvent(s1, ev0, 0);
    cudaStreamWaitEvent(s2, ev0, 0);

    // main: router path (zero fused into router_logits)
    router_logits_kernel<<<T_TOT / 128, 256, R_SMEM>>>(x, gate_w);
    topk_kernel<<<T_TOT / 256, 256>>>();
    prefix_kernel<<<1, 32>>>();

    // s1: conversions needed by gemm1
    tohalf_kernel<<<2048, 256, 0, s1>>>(x,   xh,   (size_t)T_TOT * HIDDEN / 8);
    tohalf_kernel<<<4096, 256, 0, s1>>>(w13, w13h, (size_t)NUM_EXPERTS * 2 * INTER * HIDDEN / 8);
    // s2: conversion needed only by gemm2 (hides under gemm1)
    tohalf_kernel<<<4096, 256, 0, s2>>>(w2,  w2h,  (size_t)NUM_EXPERTS * HIDDEN * INTER / 8);

    // join s1 before gemm1
    cudaEventRecord(ev1, s1);
    cudaStreamWaitEvent(0, ev1, 0);
    gemm1_kernel<<<dim3(T_TOT / 128, INTER / 64, NUM_EXPERTS), 256, SMEM_DYN>>>();

    // join s2 before gemm2
    cudaEventRecord(ev2, s2);
    cudaStreamWaitEvent(0, ev2, 0);
    gemm2_kernel<<<dim3(T_TOT / 128, HIDDEN / 128, NUM_EXPERTS), 256, SMEM_DYN>>>();

    gather_kernel<<<T_TOT, 128>>>(out);
}